// round 14
// baseline (speedup 1.0000x reference)
#include <cuda_runtime.h>
#include <math.h>
#include <stdint.h>

// ---------------- problem constants ----------------
#define Dm     512
#define DIN    1024
#define Hh     16
#define DFF    1368
#define DFFP   1408
#define N13    2816            // w1/w3 column-interleaved (2*1368 | pad)
#define NPROJ  6272            // Wz|Wx|Wb|Wc|Wdt(pad)
#define DTC    6144
#define BB     4
#define SS     512
#define TT     2048
#define NCHK   512
#define L64    64

// ---------------- static scratch ----------------
__device__ __align__(16) float g_xn  [TT*Dm];
__device__ __align__(16) float g_proj[TT*NPROJ];
__device__ __align__(16) float g_gy  [TT*DIN];
__device__ __align__(16) float g_x1  [TT*Dm];
__device__ __align__(16) float g_xn2 [TT*Dm];
__device__ __align__(16) float g_g2  [TT*DFFP];
__device__ __align__(16) float g_WpT [NPROJ*Dm];   // [n][k]
__device__ __align__(16) float g_W13T[N13*Dm];     // [n][k], n interleaved w1/w3
__device__ __align__(16) float g_WoT [Dm*DIN];
__device__ __align__(16) float g_W2T [Dm*DFFP];
__device__ __align__(16) float g_S   [NCHK*8192];
__device__ __align__(16) float g_h0  [NCHK*8192];
__device__ __align__(16) float g_cd  [TT*Hh];

// ---------------- helpers ----------------
__device__ __forceinline__ uint32_t f2tf32(float v) {
    uint32_t u; asm("cvt.rna.tf32.f32 %0, %1;" : "=r"(u) : "f"(v)); return u;
}
__device__ __forceinline__ float rnd_tf32(float v) { return __uint_as_float(f2tf32(v)); }

#define CP16(dst, src) asm volatile("cp.async.cg.shared.global [%0], [%1], 16;\n" :: "r"(dst), "l"(src))
#define CP_COMMIT()    asm volatile("cp.async.commit_group;\n")
#define CP_WAIT(n)     asm volatile("cp.async.wait_group %0;\n" :: "n"(n))

__device__ __forceinline__ void mma_tf32(float* c, const uint32_t* a, const uint32_t* b) {
    asm volatile("mma.sync.aligned.m16n8k8.row.col.f32.tf32.tf32.f32 "
        "{%0,%1,%2,%3}, {%4,%5,%6,%7}, {%8,%9}, {%0,%1,%2,%3};"
        : "+f"(c[0]), "+f"(c[1]), "+f"(c[2]), "+f"(c[3])
        : "r"(a[0]), "r"(a[1]), "r"(a[2]), "r"(a[3]), "r"(b[0]), "r"(b[1]));
}
__device__ __forceinline__ void ldsm_x4(uint32_t& r0, uint32_t& r1, uint32_t& r2, uint32_t& r3,
                                        uint32_t addr) {
    asm volatile("ldmatrix.sync.aligned.m8n8.x4.shared.b16 {%0,%1,%2,%3}, [%4];"
        : "=r"(r0), "=r"(r1), "=r"(r2), "=r"(r3) : "r"(addr));
}
__device__ __forceinline__ float2 ffma2(float2 a, float2 b, float2 c) {
    unsigned long long A = *reinterpret_cast<unsigned long long*>(&a);
    unsigned long long B = *reinterpret_cast<unsigned long long*>(&b);
    unsigned long long C = *reinterpret_cast<unsigned long long*>(&c);
    unsigned long long D;
    asm("fma.rn.f32x2 %0, %1, %2, %3;" : "=l"(D) : "l"(A), "l"(B), "l"(C));
    return *reinterpret_cast<float2*>(&D);
}
#define F2(a,b) make_float2((a),(b))

// ---------------- transposed pack: Wp | W13 (w1/w3 interleaved) ----------------
__global__ __launch_bounds__(256)
void tpack_kernel(const float* __restrict__ Wz, const float* __restrict__ Wx,
                  const float* __restrict__ Wb, const float* __restrict__ Wc,
                  const float* __restrict__ Wdt,
                  const float* __restrict__ w1, const float* __restrict__ w3) {
    __shared__ float tile[32][33];
    const int bx = blockIdx.x, by = blockIdx.y;
    const int tx = threadIdx.x & 31, ty = threadIdx.x >> 5;
    const int r0 = by * 32;
    int mat, c0;
    if (bx < 196) { mat = 0; c0 = bx * 32; }
    else          { mat = 1; c0 = (bx - 196) * 32; }

    #pragma unroll
    for (int i = 0; i < 32; i += 8) {
        int r = r0 + ty + i, c = c0 + tx;
        float v;
        if (mat == 0) {
            if      (c < 1024) v = Wz[r * 1024 + c];
            else if (c < 2048) v = Wx[r * 1024 + c - 1024];
            else if (c < 4096) v = Wb[r * 2048 + c - 2048];
            else if (c < 6144) v = Wc[r * 2048 + c - 4096];
            else if (c < 6160) v = Wdt[r * 16 + c - 6144];
            else               v = 0.f;
        } else {
            v = 0.f;
            if (c < 2 * DFF) {
                const float* w = (c & 1) ? w3 : w1;
                v = w[r * DFF + (c >> 1)];
            }
        }
        tile[ty + i][tx] = v;
    }
    __syncthreads();
    float* out = (mat == 0) ? g_WpT : g_W13T;
    #pragma unroll
    for (int i = 0; i < 32; i += 8)
        out[(size_t)(c0 + ty + i) * Dm + r0 + tx] = rnd_tf32(tile[tx][ty + i]);
}

// ---------------- transposed pack: Wout, w2 ----------------
__global__ __launch_bounds__(256)
void tpack_sk_kernel(const float* __restrict__ Wout, const float* __restrict__ w2) {
    __shared__ float tile[32][33];
    const int bx = blockIdx.x, by = blockIdx.y;
    const int tx = threadIdx.x & 31, ty = threadIdx.x >> 5;
    const int mat = (bx < 16) ? 0 : 1;
    const int c0 = ((mat == 0) ? bx : bx - 16) * 32;
    const int r0 = by * 32;
    if (mat == 0 && r0 >= DIN) return;

    #pragma unroll
    for (int i = 0; i < 32; i += 8) {
        int r = r0 + ty + i, c = c0 + tx;
        float v;
        if (mat == 0) v = Wout[(size_t)r * 512 + c];
        else          v = (r < DFF) ? w2[(size_t)r * 512 + c] : 0.f;
        tile[ty + i][tx] = v;
    }
    __syncthreads();
    float* out = mat ? g_W2T : g_WoT;
    const int ld = mat ? DFFP : DIN;
    #pragma unroll
    for (int i = 0; i < 32; i += 8)
        out[(size_t)(c0 + ty + i) * ld + r0 + tx] = rnd_tf32(tile[tx][ty + i]);
}

// ---------------- rmsnorm ----------------
__global__ __launch_bounds__(128)
void rmsnorm_kernel(const float* __restrict__ x, const float* __restrict__ w,
                    const float* __restrict__ mask, float* __restrict__ out, int useMask) {
    int t = blockIdx.x;
    const float4* xr = (const float4*)(x + (size_t)t * Dm);
    float4 v = xr[threadIdx.x];
    float s = v.x * v.x + v.y * v.y + v.z * v.z + v.w * v.w;
    __shared__ float red[4];
    #pragma unroll
    for (int o = 16; o; o >>= 1) s += __shfl_down_sync(0xFFFFFFFFu, s, o);
    if ((threadIdx.x & 31) == 0) red[threadIdx.x >> 5] = s;
    __syncthreads();
    float tot = red[0] + red[1] + red[2] + red[3];
    float inv = rsqrtf(tot / (float)Dm + 1e-6f);
    float m = useMask ? mask[t] : 1.f;
    inv *= m;
    float4 wv = ((const float4*)w)[threadIdx.x];
    float4 o;
    o.x = rnd_tf32(v.x * inv * wv.x);
    o.y = rnd_tf32(v.y * inv * wv.y);
    o.z = rnd_tf32(v.z * inv * wv.z);
    o.w = rnd_tf32(v.w * inv * wv.w);
    ((float4*)(out + (size_t)t * Dm))[threadIdx.x] = o;
}

// ---------------- tf32 GEMM, 128x128, 512 threads (16 warps, 8x2), ldmatrix ----------------
// mode 0: C=acc   1: C=res+acc*mask[row]   2: C=(res+acc)*mask
// mode 5: fused swiglu (interleaved w1/w3 cols), output stride N/2
#define NSTAGE 3
#define ASZ (128*36)
#define BSZ (128*36)
__global__ __launch_bounds__(512, 2)
void mma_gemm(const float* __restrict__ A, const float* __restrict__ BT,
              float* __restrict__ C, int M, int N, int K,
              int mode, const float* __restrict__ res, const float* __restrict__ mask) {
    extern __shared__ uint32_t smem[];
    uint32_t* Asm = smem;
    uint32_t* Bsm = smem + NSTAGE * ASZ;
    const uint32_t as_sh = (uint32_t)__cvta_generic_to_shared(Asm);
    const uint32_t bs_sh = (uint32_t)__cvta_generic_to_shared(Bsm);

    const int bm = blockIdx.y * 128, bn = blockIdx.x * 128;
    const int tid = threadIdx.x;
    const int lane = tid & 31, w = tid >> 5;      // 16 warps
    const int wm = (w >> 1) * 16, wn = (w & 1) * 64;
    const int g = lane >> 2, tg = lane & 3;
    const int kIter = K >> 5;

    const int am0 = tid >> 3, akq = (tid & 7) * 4;   // 0..63 rows, 2 iters of 64

    auto issue = [&](int it) {
        const int st = it % NSTAGE;
        const int k0 = it << 5;
        #pragma unroll
        for (int i = 0; i < 2; i++) {
            int m = am0 + i * 64;
            CP16(as_sh + (st * ASZ + m * 36 + akq) * 4,
                 A + (size_t)(bm + m) * K + k0 + akq);
        }
        #pragma unroll
        for (int i = 0; i < 2; i++) {
            int n = am0 + i * 64;
            CP16(bs_sh + (st * BSZ + n * 36 + akq) * 4,
                 BT + (size_t)(bn + n) * K + k0 + akq);
        }
        CP_COMMIT();
    };

    const int tq = lane & 7, sel = lane >> 3;
    uint32_t aBase, bBase[4];
    aBase = as_sh + (((wm + (sel & 1) * 8 + tq) * 36 + (sel >> 1) * 4) << 2);
    #pragma unroll
    for (int j = 0; j < 4; j++)
        bBase[j] = bs_sh + (((wn + j * 16 + (sel >> 1) * 8 + tq) * 36 + (sel & 1) * 4) << 2);

    float acc[8][4];
    #pragma unroll
    for (int nt = 0; nt < 8; nt++)
        #pragma unroll
        for (int q = 0; q < 4; q++) acc[nt][q] = 0.f;

    issue(0); issue(1);

    for (int it = 0; it < kIter; it++) {
        if (it == kIter - 1) { CP_WAIT(0); } else { CP_WAIT(1); }
        __syncthreads();
        if (it + 2 < kIter) issue(it + 2);

        const uint32_t soA = (uint32_t)((it % NSTAGE) * ASZ) << 2;
        const uint32_t soB = (uint32_t)((it % NSTAGE) * BSZ) << 2;
        #pragma unroll
        for (int kh = 0; kh < 4; kh++) {
            const uint32_t kbb = (uint32_t)(kh * 8) << 2;
            uint32_t af[4];
            ldsm_x4(af[0], af[1], af[2], af[3], aBase + soA + kbb);
            #pragma unroll
            for (int j = 0; j < 4; j++) {
                uint32_t b0, b1, b2, b3;
                ldsm_x4(b0, b1, b2, b3, bBase[j] + soB + kbb);
                uint32_t bf0[2] = {b0, b1};
                uint32_t bf1[2] = {b2, b3};
                mma_tf32(acc[2 * j],     af, bf0);
                mma_tf32(acc[2 * j + 1], af, bf1);
            }
        }
    }

    if (mode == 5) {
        const int halfN = N >> 1;
        #pragma unroll
        for (int nt = 0; nt < 8; nt++) {
            int r0 = bm + wm + g;
            int c0 = bn + wn + nt * 8 + tg * 2;      // even
            #pragma unroll
            for (int half = 0; half < 2; half++) {
                int r = r0 + half * 8;
                float v0 = acc[nt][half * 2 + 0];
                float v1 = acc[nt][half * 2 + 1];
                float sv = v0 / (1.f + expf(-v0));
                C[(size_t)r * halfN + (c0 >> 1)] = rnd_tf32(sv * v1);
            }
        }
        return;
    }

    #pragma unroll
    for (int nt = 0; nt < 8; nt++) {
        int r0 = bm + wm + g;
        int c0 = bn + wn + nt * 8 + tg * 2;
        #pragma unroll
        for (int half = 0; half < 2; half++) {
            int r = r0 + half * 8;
            float mk = (mode == 1 || mode == 2) ? mask[r] : 0.f;
            #pragma unroll
            for (int q = 0; q < 2; q++) {
                int c = c0 + q;
                float v = acc[nt][half * 2 + q];
                size_t idx = (size_t)r * N + c;
                float o;
                if (mode == 0)      o = v;
                else if (mode == 1) o = res[idx] + v * mk;
                else                o = (res[idx] + v) * mk;
                C[idx] = o;
            }
        }
    }
}

// ---------------- tf32 GEMM, 64x64 tile, ldmatrix (skinny: Wout, w2) ----------------
#define ASZK (64*36)
#define BSZK (64*36)
__global__ __launch_bounds__(256, 3)
void mma_gemm_sk(const float* __restrict__ A, const float* __restrict__ BT,
                 float* __restrict__ C, int M, int N, int K,
                 int mode, const float* __restrict__ res, const float* __restrict__ mask) {
    extern __shared__ uint32_t smem[];
    uint32_t* Asm = smem;
    uint32_t* Bsm = smem + NSTAGE * ASZK;
    const uint32_t as_sh = (uint32_t)__cvta_generic_to_shared(Asm);
    const uint32_t bs_sh = (uint32_t)__cvta_generic_to_shared(Bsm);

    const int bm = blockIdx.y * 64, bn = blockIdx.x * 64;
    const int tid = threadIdx.x;
    const int lane = tid & 31, w = tid >> 5;
    const int wm = (w & 1) * 32, wn = (w >> 1) * 16;
    const int g = lane >> 2, tg = lane & 3;
    const int kIter = K >> 5;

    const int am0 = tid >> 3, akq = (tid & 7) * 4;

    auto issue = [&](int it) {
        const int st = it % NSTAGE;
        const int k0 = it << 5;
        #pragma unroll
        for (int i = 0; i < 2; i++) {
            int m = am0 + i * 32;
            CP16(as_sh + (st * ASZK + m * 36 + akq) * 4,
                 A + (size_t)(bm + m) * K + k0 + akq);
        }
        #pragma unroll
        for (int i = 0; i < 2; i++) {
            int n = am0 + i * 32;
            CP16(bs_sh + (st * BSZK + n * 36 + akq) * 4,
                 BT + (size_t)(bn + n) * K + k0 + akq);
        }
        CP_COMMIT();
    };

    const int tq = lane & 7, sel = lane >> 3;
    uint32_t aBase[2], bBase;
    #pragma unroll
    for (int mt = 0; mt < 2; mt++)
        aBase[mt] = as_sh + (((wm + mt * 16 + (sel & 1) * 8 + tq) * 36 + (sel >> 1) * 4) << 2);
    bBase = bs_sh + (((wn + (sel >> 1) * 8 + tq) * 36 + (sel & 1) * 4) << 2);

    float acc[2][2][4];
    #pragma unroll
    for (int mt = 0; mt < 2; mt++)
        #pragma unroll
        for (int nt = 0; nt < 2; nt++)
            #pragma unroll
            for (int q = 0; q < 4; q++) acc[mt][nt][q] = 0.f;

    issue(0); issue(1);

    for (int it = 0; it < kIter; it++) {
        if (it == kIter - 1) { CP_WAIT(0); } else { CP_WAIT(1); }
        __syncthreads();
        if (it + 2 < kIter) issue(it + 2);

        const uint32_t soA = (uint32_t)((it % NSTAGE) * ASZK) << 2;
        const uint32_t soB = (uint32_t)((it % NSTAGE) * BSZK) << 2;
        #pragma unroll
        for (int kh = 0; kh < 4; kh++) {
            const uint32_t kbb = (uint32_t)(kh * 8) << 2;
            uint32_t af[2][4];
            ldsm_x4(af[0][0], af[0][1], af[0][2], af[0][3], aBase[0] + soA + kbb);
            ldsm_x4(af[1][0], af[1][1], af[1][2], af[1][3], aBase[1] + soA + kbb);
            uint32_t b0, b1, b2, b3;
            ldsm_x4(b0, b1, b2, b3, bBase + soB + kbb);
            uint32_t bf0[2] = {b0, b1};
            uint32_t bf1[2] = {b2, b3};
            mma_tf32(acc[0][0], af[0], bf0);
            mma_tf32(acc[1][0], af[1], bf0);
            mma_tf32(acc[0][1], af[0], bf1);
            mma_tf32(acc[1][1], af[1], bf1);
        }
    }

    #pragma unroll
    for (int mt = 0; mt < 2; mt++) {
        #pragma unroll
        for (int nt = 0; nt < 2; nt++) {
            int r0 = bm + wm + mt * 16 + g;
            int c0 = bn + wn + nt * 8 + tg * 2;
            #pragma unroll
            for (int half = 0; half < 2; half++) {
                int r = r0 + half * 8;
                float mk = (mode == 1 || mode == 2) ? mask[r] : 0.f;
                #pragma unroll
                for (int q = 0; q < 2; q++) {
                    int c = c0 + q;
                    float v = acc[mt][nt][half * 2 + q];
                    size_t idx = (size_t)r * N + c;
                    float o;
                    if (mode == 0)      o = v;
                    else if (mode == 1) o = res[idx] + v * mk;
                    else                o = (res[idx] + v) * mk;
                    C[idx] = o;
                }
            }
        }
    }
}

// ================= chunked SSM scan (known-good fp32) =================
__global__ __launch_bounds__(256, 2)
void scan_pass1(const float* __restrict__ proj, const float* __restrict__ dtb,
                const float* __restrict__ A_log,
                float* __restrict__ Sg, float* __restrict__ cdg) {
    const int blk = blockIdx.x;
    const int c = blk & 7, bh = blk >> 3, h = bh & 15, b = bh >> 4;
    const int tid = threadIdx.x;
    const int tok0 = b * SS + c * L64;

    extern __shared__ float sm1[];
    float* cds = sm1;
    float* wts = sm1 + 64;
    float* Bw  = sm1 + 128;
    float* Ud  = Bw + 64 * 132;

    const float eA = expf(A_log[h]);

    if (tid < 64) {
        float raw = proj[(size_t)(tok0 + tid) * NPROJ + DTC + h] + dtb[h];
        cds[tid] = (raw > 20.f) ? raw : log1pf(expf(raw));
    }
    __syncthreads();
    #pragma unroll
    for (int off = 1; off < 64; off <<= 1) {
        float v = (tid < 64 && tid >= off) ? cds[tid - off] : 0.f;
        __syncthreads();
        if (tid < 64) cds[tid] += v;
        __syncthreads();
    }
    if (tid < 64) {
        cdg[(size_t)(tok0 + tid) * Hh + h] = cds[tid];
        wts[tid] = expf(-eA * (cds[63] - cds[tid]));
    }
    __syncthreads();

    for (int i = tid; i < 64 * 32; i += 256) {
        int t = i >> 5, rq = (i & 31) << 2;
        float4 bv = *(const float4*)&proj[(size_t)(tok0 + t) * NPROJ + 2048 + h * 128 + rq];
        float w = wts[t];
        float4 o; o.x = bv.x * w; o.y = bv.y * w; o.z = bv.z * w; o.w = bv.w * w;
        *(float4*)&Bw[t * 132 + rq] = o;
    }
    for (int i = tid; i < 64 * 16; i += 256) {
        int t = i >> 4, pq = (i & 15) << 2;
        float4 uv = *(const float4*)&proj[(size_t)(tok0 + t) * NPROJ + 1024 + h * 64 + pq];
        float dtv = (t == 0) ? cds[0] : (cds[t] - cds[t - 1]);
        float4 o; o.x = uv.x * dtv; o.y = uv.y * dtv; o.z = uv.z * dtv; o.w = uv.w * dtv;
        *(float4*)&Ud[t * 68 + pq] = o;
    }
    __syncthreads();

    const int rn0 = (tid >> 3) * 4, p0 = (tid & 7) * 8;
    float2 acc[4][4];
    #pragma unroll
    for (int r = 0; r < 4; r++)
        #pragma unroll
        for (int j = 0; j < 4; j++) acc[r][j] = F2(0.f, 0.f);

    for (int t = 0; t < 64; t++) {
        float4 bb = *(const float4*)&Bw[t * 132 + rn0];
        float4 u0 = *(const float4*)&Ud[t * 68 + p0];
        float4 u1 = *(const float4*)&Ud[t * 68 + p0 + 4];
        float br[4] = {bb.x, bb.y, bb.z, bb.w};
        float2 ua = F2(u0.x, u0.y), ub = F2(u0.z, u0.w);
        float2 uc = F2(u1.x, u1.y), ue = F2(u1.z, u1.w);
        #pragma unroll
        for (int r = 0; r < 4; r++) {
            float2 b2 = F2(br[r], br[r]);
            acc[r][0] = ffma2(b2, ua, acc[r][0]);
            acc[r][1] = ffma2(b2, ub, acc[r][1]);
            acc[r][2] = ffma2(b2, uc, acc[r][2]);
            acc[r][3] = ffma2(b2, ue, acc[r][3]);
        }
    }
    float* Sb = Sg + (size_t)blk * 8192;
    #pragma unroll
    for (int r = 0; r < 4; r++) {
        float4 o0; o0.x = acc[r][0].x; o0.y = acc[r][0].y; o0.z = acc[r][1].x; o0.w = acc[r][1].y;
        float4 o1; o1.x = acc[r][2].x; o1.y = acc[r][2].y; o1.z = acc[r][3].x; o1.w = acc[r][3].y;
        *(float4*)&Sb[(rn0 + r) * 64 + p0]     = o0;
        *(float4*)&Sb[(rn0 + r) * 64 + p0 + 4] = o1;
    }
}

__global__ __launch_bounds__(256)
void scan_pass2(const float* __restrict__ Sg, const float* __restrict__ cdg,
                const float* __restrict__ A_log, float* __restrict__ h0g) {
    const int gidx = blockIdx.x * blockDim.x + threadIdx.x;
    const int bh = gidx >> 11, e4 = (gidx & 2047) << 2;
    const int h = bh & 15, b = bh >> 4;
    const float eA = expf(A_log[h]);
    float4 st = make_float4(0.f, 0.f, 0.f, 0.f);
    #pragma unroll
    for (int c = 0; c < 8; c++) {
        size_t base = ((size_t)(bh * 8 + c)) * 8192 + e4;
        *(float4*)&h0g[base] = st;
        float q = expf(-eA * cdg[(size_t)(b * SS + c * L64 + 63) * Hh + h]);
        float4 s4 = *(const float4*)&Sg[base];
        st.x = q * st.x + s4.x;
        st.y = q * st.y + s4.y;
        st.z = q * st.z + s4.z;
        st.w = q * st.w + s4.w;
    }
}

__global__ __launch_bounds__(256, 2)
void scan_pass3(const float* __restrict__ proj, const float* __restrict__ cdg,
                const float* __restrict__ h0g, const float* __restrict__ A_log,
                const float* __restrict__ Dskip, float* __restrict__ gy) {
    const int blk = blockIdx.x;
    const int c = blk & 7, bh = blk >> 3, h = bh & 15, b = bh >> 4;
    const int tid = threadIdx.x;
    const int tok0 = b * SS + c * L64;
    const float eA  = expf(A_log[h]);
    const float dsk = Dskip[h];

    extern __shared__ float sm3[];
    float* Csm  = sm3;
    float* Bsm  = Csm + 64 * 132;
    float* Udsm = Bsm + 64 * 132;
    float* Msm  = Udsm + 64 * 68;
    float* cds  = Msm + 64 * 68;

    if (tid < 64) cds[tid] = cdg[(size_t)(tok0 + tid) * Hh + h];
    for (int i = tid; i < 64 * 32; i += 256) {
        int t = i >> 5, rq = (i & 31) << 2;
        const float* src = &proj[(size_t)(tok0 + t) * NPROJ + 2048 + h * 128 + rq];
        *(float4*)&Bsm[t * 132 + rq] = *(const float4*)src;
        *(float4*)&Csm[t * 132 + rq] = *(const float4*)(src + 2048);
    }
    __syncthreads();
    for (int i = tid; i < 64 * 16; i += 256) {
        int t = i >> 4, pq = (i & 15) << 2;
        float4 uv = *(const float4*)&proj[(size_t)(tok0 + t) * NPROJ + 1024 + h * 64 + pq];
        float dtv = (t == 0) ? cds[0] : (cds[t] - cds[t - 1]);
        float4 o; o.x = uv.x * dtv; o.y = uv.y * dtv; o.z = uv.z * dtv; o.w = uv.w * dtv;
        *(float4*)&Udsm[t * 68 + pq] = o;
    }
    __syncthreads();

    const int t0 = (tid >> 4) * 4;
    const int q0 = (tid & 15) * 4;

    float2 ga[4][4];
    #pragma unroll
    for (int i = 0; i < 4; i++)
        #pragma unroll
        for (int j = 0; j < 4; j++) ga[i][j] = F2(0.f, 0.f);
    for (int k = 0; k < 128; k += 4) {
        float4 cr[4], br[4];
        #pragma unroll
        for (int r = 0; r < 4; r++) {
            cr[r] = *(const float4*)&Csm[(t0 + r) * 132 + k];
            br[r] = *(const float4*)&Bsm[(q0 + r) * 132 + k];
        }
        #pragma unroll
        for (int tt = 0; tt < 4; tt++) {
            float2 c2a = F2(cr[tt].x, cr[tt].y), c2b = F2(cr[tt].z, cr[tt].w);
            #pragma unroll
            for (int qq = 0; qq < 4; qq++) {
                ga[tt][qq] = ffma2(c2a, F2(br[qq].x, br[qq].y), ga[tt][qq]);
                ga[tt][qq] = ffma2(c2b, F2(br[qq].z, br[qq].w), ga[tt][qq]);
            }
        }
    }
    #pragma unroll
    for (int tt = 0; tt < 4; tt++) {
        int t = t0 + tt;
        #pragma unroll
        for (int qq = 0; qq < 4; qq++) {
            int q = q0 + qq;
            float g = ga[tt][qq].x + ga[tt][qq].y;
            float w = (q <= t) ? __expf(-eA * (cds[t] - cds[q])) : 0.f;
            Msm[t * 68 + q] = g * w;
        }
    }
    __syncthreads();

    const float* h0b = &h0g[(size_t)blk * 8192];
    float4 hreg[4];
    #pragma unroll
    for (int j = 0; j < 4; j++) {
        int i = tid + j * 256;
        int rn = i >> 4, pq = (i & 15) << 2;
        hreg[j] = *(const float4*)&h0b[rn * 64 + pq];
    }

    const int p0 = q0;
    float2 ya[4][2], yb[4][2];
    #pragma unroll
    for (int i = 0; i < 4; i++) {
        ya[i][0] = F2(0.f, 0.f); ya[i][1] = F2(0.f, 0.f);
        yb[i][0] = F2(0.f, 0.f); yb[i][1] = F2(0.f, 0.f);
    }
    for (int q = 0; q < 64; q += 4) {
        float4 mr[4], ur[4];
        #pragma unroll
        for (int r = 0; r < 4; r++) mr[r] = *(const float4*)&Msm[(t0 + r) * 68 + q];
        #pragma unroll
        for (int j = 0; j < 4; j++) ur[j] = *(const float4*)&Udsm[(q + j) * 68 + p0];
        #pragma unroll
        for (int tt = 0; tt < 4; tt++) {
            float4 m4 = mr[tt];
            ya[tt][0] = ffma2(F2(m4.x, m4.x), F2(ur[0].x, ur[0].y), ya[tt][0]);
            ya[tt][1] = ffma2(F2(m4.x, m4.x), F2(ur[0].z, ur[0].w), ya[tt][1]);
            ya[tt][0] = ffma2(F2(m4.y, m4.y), F2(ur[1].x, ur[1].y), ya[tt][0]);
            ya[tt][1] = ffma2(F2(m4.y, m4.y), F2(ur[1].z, ur[1].w), ya[tt][1]);
            ya[tt][0] = ffma2(F2(m4.z, m4.z), F2(ur[2].x, ur[2].y), ya[tt][0]);
            ya[tt][1] = ffma2(F2(m4.z, m4.z), F2(ur[2].z, ur[2].w), ya[tt][1]);
            ya[tt][0] = ffma2(F2(m4.w, m4.w), F2(ur[3].x, ur[3].y), ya[tt][0]);
            ya[tt][1] = ffma2(F2(m4.w, m4.w), F2(ur[3].z, ur[3].w), ya[tt][1]);
        }
    }

    float* h0s = Bsm;
    #pragma unroll
    for (int j = 0; j < 4; j++) {
        int i = tid + j * 256;
        int rn = i >> 4, pq = (i & 15) << 2;
        *(float4*)&h0s[rn * 68 + pq] = hreg[j];
    }
    __syncthreads();

    for (int rn = 0; rn < 64; rn += 4) {
        float4 cr[4], hr[4];
        #pragma unroll
        for (int r = 0; r < 4; r++) cr[r] = *(const float4*)&Csm[(t0 + r) * 132 + rn];
        #pragma unroll
        for (int j = 0; j < 4; j++) hr[j] = *(const float4*)&h0s[(rn + j) * 68 + p0];
        #pragma unroll
        for (int tt = 0; tt < 4; tt++) {
            float4 c4 = cr[tt];
            yb[tt][0] = ffma2(F2(c4.x, c4.x), F2(hr[0].x, hr[0].y), yb[tt][0]);
            yb[tt][1] = ffma2(F2(c4.x, c4.x), F2(hr[0].z, hr[0].w), yb[tt][1]);
            yb[tt][0] = ffma2(F2(c4.y, c4.y), F2(hr[1].x, hr[1].y), yb[tt][0]);
            yb[tt][1] = ffma2(F2(c4.y, c4.y), F2(hr[1].z, hr[1].w), yb[tt][1]);
            yb[tt][0] = ffma2(F2(c4.z, c4.z), F2(hr[2].x, hr[2].y), yb[tt][0]);
            yb[tt][1] = ffma2(F2(c4.z, c4.z), F2(hr[2].z, hr[2].w), yb[tt][1]);
            yb[tt][0] = ffma2(F2(c4.w, c4.w), F2(hr[3].x, hr[3].y), yb[tt][0]);
            yb[tt][1] = ffma2(F2(c4.w, c4.w), F2(hr[3].z, hr[3].w), yb[tt][1]);
        }
    }
    __syncthreads();
    #pragma unroll
    for (int j = 0; j < 4; j++) {
        int i = tid + j * 256;
        int rn = i >> 4, pq = (i & 15) << 2;
        *(float4*)&h0s[rn * 68 + pq] = *(const float4*)&h0b[(64 + rn) * 64 + pq];
    }
    __syncthreads();
    for (int rn = 0; rn < 64; rn += 4) {
        float4 cr[4], hr[4];
        #pragma unroll
        for (int r = 0; r < 4; r++) cr[r] = *(const float4*)&Csm[(t0 + r) * 132 + 64 + rn];
        #pragma unroll
        for (int j = 0; j < 4; j++) hr[j] = *(const float4*)&h0s[(rn + j) * 68 + p0];
        #pragma unroll
        for (int tt = 0; tt < 4; tt++) {
            float4 c4 = cr[tt];
            yb[tt][0] = ffma2(F2(c4.x, c4.x), F2(hr[0].x, hr[0].y), yb[tt][0]);
            yb[tt][1] = ffma2(F2(c4.x, c4.x), F2(hr[0].z, hr[0].w), yb[tt][1]);
            yb[tt][0] = ffma2(F2(c4.y, c4.y), F2(hr[1].x, hr[1].y), yb[tt][0]);
            yb[tt][1] = ffma2(F2(c4.y, c4.y), F2(hr[1].z, hr[1].w), yb[tt][1]);
            yb[tt][0] = ffma2(F2(c4.z, c4.z), F2(hr[2].x, hr[2].y), yb[tt][0]);
            yb[tt][1] = ffma2(F2(c4.z, c4.z), F2(hr[2].z, hr[2].w), yb[tt][1]);
            yb[tt][0] = ffma2(F2(c4.w, c4.w), F2(hr[3].x, hr[3].y), yb[tt][0]);
            yb[tt][1] = ffma2(F2(c4.w, c4.w), F2(hr[3].z, hr[3].w), yb[tt][1]);
        }
    }

    #pragma unroll
    for (int tt = 0; tt < 4; tt++) {
        int t = t0 + tt;
        float Qt = __expf(-eA * cds[t]);
        size_t token = (size_t)(tok0 + t);
        float4 uv = *(const float4*)&proj[token * NPROJ + 1024 + h * 64 + p0];
        float4 zv = *(const float4*)&proj[token * NPROJ + h * 64 + p0];
        float y0 = ya[tt][0].x + Qt * yb[tt][0].x;
        float y1 = ya[tt][0].y + Qt * yb[tt][0].y;
        float y2 = ya[tt][1].x + Qt * yb[tt][1].x;
        float y3 = ya[tt][1].y + Qt * yb[tt][1].y;
        float4 o;
        o.x = rnd_tf32((y0 + uv.x * dsk) * (zv.x / (1.f + expf(-zv.x))));
        o.y = rnd_tf32((y1 + uv.y * dsk) * (zv.y / (1.f + expf(-zv.y))));
        o.z = rnd_tf32((y2 + uv.z * dsk) * (zv.z / (1.f + expf(-zv.z))));
        o.w = rnd_tf32((y3 + uv.w * dsk) * (zv.w / (1.f + expf(-zv.w))));
        *(float4*)&gy[token * DIN + h * 64 + p0] = o;
    }
}

// ---------------- launch ----------------
extern "C" void kernel_launch(void* const* d_in, const int* in_sizes, int n_in,
                              void* d_out, int out_size) {
    const float* x      = (const float*)d_in[0];
    const float* mask   = (const float*)d_in[1];
    const float* n1w    = (const float*)d_in[2];
    const float* n2w    = (const float*)d_in[3];
    const float* Wz     = (const float*)d_in[4];
    const float* Wx     = (const float*)d_in[5];
    const float* Wb     = (const float*)d_in[6];
    const float* Wc     = (const float*)d_in[7];
    const float* Wdt    = (const float*)d_in[8];
    const float* dtb    = (const float*)d_in[9];
    const float* A_log  = (const float*)d_in[10];
    const float* D_skip = (const float*)d_in[11];
    const float* Wout   = (const float*)d_in[12];
    const float* w1     = (const float*)d_in[13];
    const float* w2     = (const float*)d_in[14];
    const float* w3     = (const float*)d_in[15];
    float* out = (float*)d_out;

    float *xn, *proj, *gy, *x1, *xn2, *g2;
    float *WpT, *W13T, *WoT, *W2T, *Sg, *h0g, *cdg;
    cudaGetSymbolAddress((void**)&xn,   g_xn);
    cudaGetSymbolAddress((void**)&proj, g_proj);
    cudaGetSymbolAddress((void**)&gy,   g_gy);
    cudaGetSymbolAddress((void**)&x1,   g_x1);
    cudaGetSymbolAddress((void**)&xn2,  g_xn2);
    cudaGetSymbolAddress((void**)&g2,   g_g2);
    cudaGetSymbolAddress((void**)&WpT,  g_WpT);
    cudaGetSymbolAddress((void**)&W13T, g_W13T);
    cudaGetSymbolAddress((void**)&WoT,  g_WoT);
    cudaGetSymbolAddress((void**)&W2T,  g_W2T);
    cudaGetSymbolAddress((void**)&Sg,   g_S);
    cudaGetSymbolAddress((void**)&h0g,  g_h0);
    cudaGetSymbolAddress((void**)&cdg,  g_cd);

    const int smemMain = NSTAGE * (ASZ + BSZ) * 4;       // 110,592
    const int smemSk   = NSTAGE * (ASZK + BSZK) * 4;     // 55,296
    const int smemP1   = (128 + 64 * 132 + 64 * 68) * 4;
    const int smemP3   = (64 * 132 * 2 + 64 * 68 * 2 + 64) * 4;
    static int configured = 0;
    if (!configured) {
        cudaFuncSetAttribute(mma_gemm,    cudaFuncAttributeMaxDynamicSharedMemorySize, smemMain);
        cudaFuncSetAttribute(mma_gemm_sk, cudaFuncAttributeMaxDynamicSharedMemorySize, smemSk);
        cudaFuncSetAttribute(scan_pass1,  cudaFuncAttributeMaxDynamicSharedMemorySize, smemP1);
        cudaFuncSetAttribute(scan_pass3,  cudaFuncAttributeMaxDynamicSharedMemorySize, smemP3);
        configured = 1;
    }

    tpack_kernel<<<dim3(196 + N13/32, 16), 256>>>(Wz, Wx, Wb, Wc, Wdt, w1, w3);
    tpack_sk_kernel<<<dim3(32, 44), 256>>>(Wout, w2);
    rmsnorm_kernel<<<TT, 128>>>(x, n1w, mask, xn, 1);

    mma_gemm<<<dim3(NPROJ/128, TT/128), 512, smemMain>>>(xn, WpT, proj, TT, NPROJ, Dm, 0, nullptr, nullptr);

    scan_pass1<<<NCHK, 256, smemP1>>>(proj, dtb, A_log, Sg, cdg);
    scan_pass2<<<512, 256>>>(Sg, cdg, A_log, h0g);
    scan_pass3<<<NCHK, 256, smemP3>>>(proj, cdg, h0g, A_log, D_skip, gy);

    mma_gemm_sk<<<dim3(Dm/64, TT/64), 256, smemSk>>>(gy, WoT, x1, TT, Dm, DIN, 1, x, mask);
    rmsnorm_kernel<<<TT, 128>>>(x1, n2w, mask, xn2, 0);

    // w1/w3 interleaved GEMM with fused swiglu epilogue -> g2 directly
    mma_gemm<<<dim3(N13/128, TT/128), 512, smemMain>>>(xn2, W13T, g2, TT, N13, Dm, 5, nullptr, nullptr);
    mma_gemm_sk<<<dim3(Dm/64, TT/64), 256, smemSk>>>(g2, W2T, out, TT, Dm, DFFP, 2, x1, mask);
}

// round 15
// speedup vs baseline: 1.0493x; 1.0493x over previous
#include <cuda_runtime.h>
#include <math.h>
#include <stdint.h>

// ---------------- problem constants ----------------
#define Dm     512
#define DIN    1024
#define Hh     16
#define DFF    1368
#define DFFP   1408
#define N13    2816            // w1/w3 column-interleaved (2*1368 | pad)
#define NPROJ  6272            // Wz|Wx|Wb|Wc|Wdt(pad)
#define DTC    6144
#define BB     4
#define SS     512
#define TT     2048
#define NCHK   512
#define L64    64

// ---------------- static scratch ----------------
__device__ __align__(16) float g_xn  [TT*Dm];
__device__ __align__(16) float g_proj[TT*NPROJ];
__device__ __align__(16) float g_gy  [TT*DIN];
__device__ __align__(16) float g_x1  [TT*Dm];
__device__ __align__(16) float g_xn2 [TT*Dm];
__device__ __align__(16) float g_g2  [TT*DFFP];
__device__ __align__(16) float g_WpT [NPROJ*Dm];   // [n][k]
__device__ __align__(16) float g_W13T[N13*Dm];     // [n][k], n interleaved w1/w3
__device__ __align__(16) float g_WoT [Dm*DIN];
__device__ __align__(16) float g_W2T [Dm*DFFP];
__device__ __align__(16) float g_S   [NCHK*8192];
__device__ __align__(16) float g_h0  [NCHK*8192];
__device__ __align__(16) float g_cd  [TT*Hh];

// ---------------- helpers ----------------
__device__ __forceinline__ uint32_t f2tf32(float v) {
    uint32_t u; asm("cvt.rna.tf32.f32 %0, %1;" : "=r"(u) : "f"(v)); return u;
}
__device__ __forceinline__ float rnd_tf32(float v) { return __uint_as_float(f2tf32(v)); }

#define CP16(dst, src) asm volatile("cp.async.cg.shared.global [%0], [%1], 16;\n" :: "r"(dst), "l"(src))
#define CP_COMMIT()    asm volatile("cp.async.commit_group;\n")
#define CP_WAIT(n)     asm volatile("cp.async.wait_group %0;\n" :: "n"(n))

__device__ __forceinline__ void mma_tf32(float* c, const uint32_t* a, const uint32_t* b) {
    asm volatile("mma.sync.aligned.m16n8k8.row.col.f32.tf32.tf32.f32 "
        "{%0,%1,%2,%3}, {%4,%5,%6,%7}, {%8,%9}, {%0,%1,%2,%3};"
        : "+f"(c[0]), "+f"(c[1]), "+f"(c[2]), "+f"(c[3])
        : "r"(a[0]), "r"(a[1]), "r"(a[2]), "r"(a[3]), "r"(b[0]), "r"(b[1]));
}
__device__ __forceinline__ void ldsm_x4(uint32_t& r0, uint32_t& r1, uint32_t& r2, uint32_t& r3,
                                        uint32_t addr) {
    asm volatile("ldmatrix.sync.aligned.m8n8.x4.shared.b16 {%0,%1,%2,%3}, [%4];"
        : "=r"(r0), "=r"(r1), "=r"(r2), "=r"(r3) : "r"(addr));
}
__device__ __forceinline__ float2 ffma2(float2 a, float2 b, float2 c) {
    unsigned long long A = *reinterpret_cast<unsigned long long*>(&a);
    unsigned long long B = *reinterpret_cast<unsigned long long*>(&b);
    unsigned long long C = *reinterpret_cast<unsigned long long*>(&c);
    unsigned long long D;
    asm("fma.rn.f32x2 %0, %1, %2, %3;" : "=l"(D) : "l"(A), "l"(B), "l"(C));
    return *reinterpret_cast<float2*>(&D);
}
#define F2(a,b) make_float2((a),(b))

// ---------------- transposed pack: Wp | W13 (w1/w3 interleaved) ----------------
__global__ __launch_bounds__(256)
void tpack_kernel(const float* __restrict__ Wz, const float* __restrict__ Wx,
                  const float* __restrict__ Wb, const float* __restrict__ Wc,
                  const float* __restrict__ Wdt,
                  const float* __restrict__ w1, const float* __restrict__ w3) {
    __shared__ float tile[32][33];
    const int bx = blockIdx.x, by = blockIdx.y;
    const int tx = threadIdx.x & 31, ty = threadIdx.x >> 5;
    const int r0 = by * 32;
    int mat, c0;
    if (bx < 196) { mat = 0; c0 = bx * 32; }
    else          { mat = 1; c0 = (bx - 196) * 32; }

    #pragma unroll
    for (int i = 0; i < 32; i += 8) {
        int r = r0 + ty + i, c = c0 + tx;
        float v;
        if (mat == 0) {
            if      (c < 1024) v = Wz[r * 1024 + c];
            else if (c < 2048) v = Wx[r * 1024 + c - 1024];
            else if (c < 4096) v = Wb[r * 2048 + c - 2048];
            else if (c < 6144) v = Wc[r * 2048 + c - 4096];
            else if (c < 6160) v = Wdt[r * 16 + c - 6144];
            else               v = 0.f;
        } else {
            v = 0.f;
            if (c < 2 * DFF) {
                const float* w = (c & 1) ? w3 : w1;
                v = w[r * DFF + (c >> 1)];
            }
        }
        tile[ty + i][tx] = v;
    }
    __syncthreads();
    float* out = (mat == 0) ? g_WpT : g_W13T;
    #pragma unroll
    for (int i = 0; i < 32; i += 8)
        out[(size_t)(c0 + ty + i) * Dm + r0 + tx] = rnd_tf32(tile[tx][ty + i]);
}

// ---------------- transposed pack: Wout, w2 ----------------
__global__ __launch_bounds__(256)
void tpack_sk_kernel(const float* __restrict__ Wout, const float* __restrict__ w2) {
    __shared__ float tile[32][33];
    const int bx = blockIdx.x, by = blockIdx.y;
    const int tx = threadIdx.x & 31, ty = threadIdx.x >> 5;
    const int mat = (bx < 16) ? 0 : 1;
    const int c0 = ((mat == 0) ? bx : bx - 16) * 32;
    const int r0 = by * 32;
    if (mat == 0 && r0 >= DIN) return;

    #pragma unroll
    for (int i = 0; i < 32; i += 8) {
        int r = r0 + ty + i, c = c0 + tx;
        float v;
        if (mat == 0) v = Wout[(size_t)r * 512 + c];
        else          v = (r < DFF) ? w2[(size_t)r * 512 + c] : 0.f;
        tile[ty + i][tx] = v;
    }
    __syncthreads();
    float* out = mat ? g_W2T : g_WoT;
    const int ld = mat ? DFFP : DIN;
    #pragma unroll
    for (int i = 0; i < 32; i += 8)
        out[(size_t)(c0 + ty + i) * ld + r0 + tx] = rnd_tf32(tile[tx][ty + i]);
}

// ---------------- rmsnorm: 2 tokens per block, independent half-block reductions ----------------
__global__ __launch_bounds__(256)
void rmsnorm_kernel(const float* __restrict__ x, const float* __restrict__ w,
                    const float* __restrict__ mask, float* __restrict__ out, int useMask) {
    const int half = threadIdx.x >> 7;               // 0/1
    const int li   = threadIdx.x & 127;
    const int t    = blockIdx.x * 2 + half;
    const float4* xr = (const float4*)(x + (size_t)t * Dm);
    float4 v = xr[li];
    float s = v.x * v.x + v.y * v.y + v.z * v.z + v.w * v.w;
    __shared__ float red[8];
    #pragma unroll
    for (int o = 16; o; o >>= 1) s += __shfl_down_sync(0xFFFFFFFFu, s, o);
    if ((threadIdx.x & 31) == 0) red[threadIdx.x >> 5] = s;
    __syncthreads();
    const float* rh = red + half * 4;
    float tot = rh[0] + rh[1] + rh[2] + rh[3];
    float inv = rsqrtf(tot / (float)Dm + 1e-6f);
    float m = useMask ? mask[t] : 1.f;
    inv *= m;
    float4 wv = ((const float4*)w)[li];
    float4 o;
    o.x = rnd_tf32(v.x * inv * wv.x);
    o.y = rnd_tf32(v.y * inv * wv.y);
    o.z = rnd_tf32(v.z * inv * wv.z);
    o.w = rnd_tf32(v.w * inv * wv.w);
    ((float4*)(out + (size_t)t * Dm))[li] = o;
}

// ---------------- tf32 GEMM, 128x128, 256 threads (8 warps 4x2), ldmatrix ----------------
// mode 0: C=acc   1: C=res+acc*mask[row]   2: C=(res+acc)*mask
// mode 5: fused swiglu (interleaved w1/w3 cols), output stride N/2
#define NSTAGE 3
#define ASZ (128*36)
#define BSZ (128*36)
__global__ __launch_bounds__(256, 2)
void mma_gemm(const float* __restrict__ A, const float* __restrict__ BT,
              float* __restrict__ C, int M, int N, int K,
              int mode, const float* __restrict__ res, const float* __restrict__ mask) {
    extern __shared__ uint32_t smem[];
    uint32_t* Asm = smem;
    uint32_t* Bsm = smem + NSTAGE * ASZ;
    const uint32_t as_sh = (uint32_t)__cvta_generic_to_shared(Asm);
    const uint32_t bs_sh = (uint32_t)__cvta_generic_to_shared(Bsm);

    const int bm = blockIdx.y * 128, bn = blockIdx.x * 128;
    const int tid = threadIdx.x;
    const int lane = tid & 31, w = tid >> 5;
    const int wm = (w >> 1) * 32, wn = (w & 1) * 64;
    const int g = lane >> 2, tg = lane & 3;
    const int kIter = K >> 5;

    const int am0 = tid >> 3, akq = (tid & 7) * 4;

    auto issue = [&](int it) {
        const int st = it % NSTAGE;
        const int k0 = it << 5;
        #pragma unroll
        for (int i = 0; i < 4; i++) {
            int m = am0 + i * 32;
            CP16(as_sh + (st * ASZ + m * 36 + akq) * 4,
                 A + (size_t)(bm + m) * K + k0 + akq);
        }
        #pragma unroll
        for (int i = 0; i < 4; i++) {
            int n = am0 + i * 32;
            CP16(bs_sh + (st * BSZ + n * 36 + akq) * 4,
                 BT + (size_t)(bn + n) * K + k0 + akq);
        }
        CP_COMMIT();
    };

    const int tq = lane & 7, sel = lane >> 3;
    uint32_t aBase[2], bBase[4];
    #pragma unroll
    for (int mt = 0; mt < 2; mt++)
        aBase[mt] = as_sh + (((wm + mt * 16 + (sel & 1) * 8 + tq) * 36 + (sel >> 1) * 4) << 2);
    #pragma unroll
    for (int j = 0; j < 4; j++)
        bBase[j] = bs_sh + (((wn + j * 16 + (sel >> 1) * 8 + tq) * 36 + (sel & 1) * 4) << 2);

    float acc[2][8][4];
    #pragma unroll
    for (int mt = 0; mt < 2; mt++)
        #pragma unroll
        for (int nt = 0; nt < 8; nt++)
            #pragma unroll
            for (int q = 0; q < 4; q++) acc[mt][nt][q] = 0.f;

    issue(0); issue(1);

    for (int it = 0; it < kIter; it++) {
        if (it == kIter - 1) { CP_WAIT(0); } else { CP_WAIT(1); }
        __syncthreads();
        if (it + 2 < kIter) issue(it + 2);

        const uint32_t soA = (uint32_t)((it % NSTAGE) * ASZ) << 2;
        const uint32_t soB = (uint32_t)((it % NSTAGE) * BSZ) << 2;
        #pragma unroll
        for (int kh = 0; kh < 4; kh++) {
            const uint32_t kbb = (uint32_t)(kh * 8) << 2;
            uint32_t af[2][4];
            ldsm_x4(af[0][0], af[0][1], af[0][2], af[0][3], aBase[0] + soA + kbb);
            ldsm_x4(af[1][0], af[1][1], af[1][2], af[1][3], aBase[1] + soA + kbb);
            #pragma unroll
            for (int j = 0; j < 4; j++) {
                uint32_t b0, b1, b2, b3;
                ldsm_x4(b0, b1, b2, b3, bBase[j] + soB + kbb);
                uint32_t bf0[2] = {b0, b1};
                uint32_t bf1[2] = {b2, b3};
                mma_tf32(acc[0][2 * j],     af[0], bf0);
                mma_tf32(acc[1][2 * j],     af[1], bf0);
                mma_tf32(acc[0][2 * j + 1], af[0], bf1);
                mma_tf32(acc[1][2 * j + 1], af[1], bf1);
            }
        }
    }

    if (mode == 5) {
        const int halfN = N >> 1;
        #pragma unroll
        for (int mt = 0; mt < 2; mt++) {
            #pragma unroll
            for (int nt = 0; nt < 8; nt++) {
                int r0 = bm + wm + mt * 16 + g;
                int c0 = bn + wn + nt * 8 + tg * 2;      // even
                #pragma unroll
                for (int half = 0; half < 2; half++) {
                    int r = r0 + half * 8;
                    float v0 = acc[mt][nt][half * 2 + 0];   // w1 col
                    float v1 = acc[mt][nt][half * 2 + 1];   // w3 col
                    float sv = v0 / (1.f + expf(-v0));
                    C[(size_t)r * halfN + (c0 >> 1)] = rnd_tf32(sv * v1);
                }
            }
        }
        return;
    }

    #pragma unroll
    for (int mt = 0; mt < 2; mt++) {
        #pragma unroll
        for (int nt = 0; nt < 8; nt++) {
            int r0 = bm + wm + mt * 16 + g;
            int c0 = bn + wn + nt * 8 + tg * 2;
            #pragma unroll
            for (int half = 0; half < 2; half++) {
                int r = r0 + half * 8;
                float mk = (mode == 1 || mode == 2) ? mask[r] : 0.f;
                #pragma unroll
                for (int q = 0; q < 2; q++) {
                    int c = c0 + q;
                    float v = acc[mt][nt][half * 2 + q];
                    size_t idx = (size_t)r * N + c;
                    float o;
                    if (mode == 0)      o = v;
                    else if (mode == 1) o = res[idx] + v * mk;
                    else                o = (res[idx] + v) * mk;
                    C[idx] = o;
                }
            }
        }
    }
}

// ---------------- tf32 GEMM, 64x64 tile, ldmatrix (skinny: Wout, w2) ----------------
#define ASZK (64*36)
#define BSZK (64*36)
__global__ __launch_bounds__(256, 3)
void mma_gemm_sk(const float* __restrict__ A, const float* __restrict__ BT,
                 float* __restrict__ C, int M, int N, int K,
                 int mode, const float* __restrict__ res, const float* __restrict__ mask) {
    extern __shared__ uint32_t smem[];
    uint32_t* Asm = smem;
    uint32_t* Bsm = smem + NSTAGE * ASZK;
    const uint32_t as_sh = (uint32_t)__cvta_generic_to_shared(Asm);
    const uint32_t bs_sh = (uint32_t)__cvta_generic_to_shared(Bsm);

    const int bm = blockIdx.y * 64, bn = blockIdx.x * 64;
    const int tid = threadIdx.x;
    const int lane = tid & 31, w = tid >> 5;
    const int wm = (w & 1) * 32, wn = (w >> 1) * 16;
    const int g = lane >> 2, tg = lane & 3;
    const int kIter = K >> 5;

    const int am0 = tid >> 3, akq = (tid & 7) * 4;

    auto issue = [&](int it) {
        const int st = it % NSTAGE;
        const int k0 = it << 5;
        #pragma unroll
        for (int i = 0; i < 2; i++) {
            int m = am0 + i * 32;
            CP16(as_sh + (st * ASZK + m * 36 + akq) * 4,
                 A + (size_t)(bm + m) * K + k0 + akq);
        }
        #pragma unroll
        for (int i = 0; i < 2; i++) {
            int n = am0 + i * 32;
            CP16(bs_sh + (st * BSZK + n * 36 + akq) * 4,
                 BT + (size_t)(bn + n) * K + k0 + akq);
        }
        CP_COMMIT();
    };

    const int tq = lane & 7, sel = lane >> 3;
    uint32_t aBase[2], bBase;
    #pragma unroll
    for (int mt = 0; mt < 2; mt++)
        aBase[mt] = as_sh + (((wm + mt * 16 + (sel & 1) * 8 + tq) * 36 + (sel >> 1) * 4) << 2);
    bBase = bs_sh + (((wn + (sel >> 1) * 8 + tq) * 36 + (sel & 1) * 4) << 2);

    float acc[2][2][4];
    #pragma unroll
    for (int mt = 0; mt < 2; mt++)
        #pragma unroll
        for (int nt = 0; nt < 2; nt++)
            #pragma unroll
            for (int q = 0; q < 4; q++) acc[mt][nt][q] = 0.f;

    issue(0); issue(1);

    for (int it = 0; it < kIter; it++) {
        if (it == kIter - 1) { CP_WAIT(0); } else { CP_WAIT(1); }
        __syncthreads();
        if (it + 2 < kIter) issue(it + 2);

        const uint32_t soA = (uint32_t)((it % NSTAGE) * ASZK) << 2;
        const uint32_t soB = (uint32_t)((it % NSTAGE) * BSZK) << 2;
        #pragma unroll
        for (int kh = 0; kh < 4; kh++) {
            const uint32_t kbb = (uint32_t)(kh * 8) << 2;
            uint32_t af[2][4];
            ldsm_x4(af[0][0], af[0][1], af[0][2], af[0][3], aBase[0] + soA + kbb);
            ldsm_x4(af[1][0], af[1][1], af[1][2], af[1][3], aBase[1] + soA + kbb);
            uint32_t b0, b1, b2, b3;
            ldsm_x4(b0, b1, b2, b3, bBase + soB + kbb);
            uint32_t bf0[2] = {b0, b1};
            uint32_t bf1[2] = {b2, b3};
            mma_tf32(acc[0][0], af[0], bf0);
            mma_tf32(acc[1][0], af[1], bf0);
            mma_tf32(acc[0][1], af[0], bf1);
            mma_tf32(acc[1][1], af[1], bf1);
        }
    }

    #pragma unroll
    for (int mt = 0; mt < 2; mt++) {
        #pragma unroll
        for (int nt = 0; nt < 2; nt++) {
            int r0 = bm + wm + mt * 16 + g;
            int c0 = bn + wn + nt * 8 + tg * 2;
            #pragma unroll
            for (int half = 0; half < 2; half++) {
                int r = r0 + half * 8;
                float mk = (mode == 1 || mode == 2) ? mask[r] : 0.f;
                #pragma unroll
                for (int q = 0; q < 2; q++) {
                    int c = c0 + q;
                    float v = acc[mt][nt][half * 2 + q];
                    size_t idx = (size_t)r * N + c;
                    float o;
                    if (mode == 0)      o = v;
                    else if (mode == 1) o = res[idx] + v * mk;
                    else                o = (res[idx] + v) * mk;
                    C[idx] = o;
                }
            }
        }
    }
}

// ================= chunked SSM scan (known-good fp32) =================
__global__ __launch_bounds__(256, 2)
void scan_pass1(const float* __restrict__ proj, const float* __restrict__ dtb,
                const float* __restrict__ A_log,
                float* __restrict__ Sg, float* __restrict__ cdg) {
    const int blk = blockIdx.x;
    const int c = blk & 7, bh = blk >> 3, h = bh & 15, b = bh >> 4;
    const int tid = threadIdx.x;
    const int tok0 = b * SS + c * L64;

    extern __shared__ float sm1[];
    float* cds = sm1;
    float* wts = sm1 + 64;
    float* Bw  = sm1 + 128;
    float* Ud  = Bw + 64 * 132;

    const float eA = expf(A_log[h]);

    if (tid < 64) {
        float raw = proj[(size_t)(tok0 + tid) * NPROJ + DTC + h] + dtb[h];
        cds[tid] = (raw > 20.f) ? raw : log1pf(expf(raw));
    }
    __syncthreads();
    #pragma unroll
    for (int off = 1; off < 64; off <<= 1) {
        float v = (tid < 64 && tid >= off) ? cds[tid - off] : 0.f;
        __syncthreads();
        if (tid < 64) cds[tid] += v;
        __syncthreads();
    }
    if (tid < 64) {
        cdg[(size_t)(tok0 + tid) * Hh + h] = cds[tid];
        wts[tid] = expf(-eA * (cds[63] - cds[tid]));
    }
    __syncthreads();

    for (int i = tid; i < 64 * 32; i += 256) {
        int t = i >> 5, rq = (i & 31) << 2;
        float4 bv = *(const float4*)&proj[(size_t)(tok0 + t) * NPROJ + 2048 + h * 128 + rq];
        float w = wts[t];
        float4 o; o.x = bv.x * w; o.y = bv.y * w; o.z = bv.z * w; o.w = bv.w * w;
        *(float4*)&Bw[t * 132 + rq] = o;
    }
    for (int i = tid; i < 64 * 16; i += 256) {
        int t = i >> 4, pq = (i & 15) << 2;
        float4 uv = *(const float4*)&proj[(size_t)(tok0 + t) * NPROJ + 1024 + h * 64 + pq];
        float dtv = (t == 0) ? cds[0] : (cds[t] - cds[t - 1]);
        float4 o; o.x = uv.x * dtv; o.y = uv.y * dtv; o.z = uv.z * dtv; o.w = uv.w * dtv;
        *(float4*)&Ud[t * 68 + pq] = o;
    }
    __syncthreads();

    const int rn0 = (tid >> 3) * 4, p0 = (tid & 7) * 8;
    float2 acc[4][4];
    #pragma unroll
    for (int r = 0; r < 4; r++)
        #pragma unroll
        for (int j = 0; j < 4; j++) acc[r][j] = F2(0.f, 0.f);

    for (int t = 0; t < 64; t++) {
        float4 bb = *(const float4*)&Bw[t * 132 + rn0];
        float4 u0 = *(const float4*)&Ud[t * 68 + p0];
        float4 u1 = *(const float4*)&Ud[t * 68 + p0 + 4];
        float br[4] = {bb.x, bb.y, bb.z, bb.w};
        float2 ua = F2(u0.x, u0.y), ub = F2(u0.z, u0.w);
        float2 uc = F2(u1.x, u1.y), ue = F2(u1.z, u1.w);
        #pragma unroll
        for (int r = 0; r < 4; r++) {
            float2 b2 = F2(br[r], br[r]);
            acc[r][0] = ffma2(b2, ua, acc[r][0]);
            acc[r][1] = ffma2(b2, ub, acc[r][1]);
            acc[r][2] = ffma2(b2, uc, acc[r][2]);
            acc[r][3] = ffma2(b2, ue, acc[r][3]);
        }
    }
    float* Sb = Sg + (size_t)blk * 8192;
    #pragma unroll
    for (int r = 0; r < 4; r++) {
        float4 o0; o0.x = acc[r][0].x; o0.y = acc[r][0].y; o0.z = acc[r][1].x; o0.w = acc[r][1].y;
        float4 o1; o1.x = acc[r][2].x; o1.y = acc[r][2].y; o1.z = acc[r][3].x; o1.w = acc[r][3].y;
        *(float4*)&Sb[(rn0 + r) * 64 + p0]     = o0;
        *(float4*)&Sb[(rn0 + r) * 64 + p0 + 4] = o1;
    }
}

__global__ __launch_bounds__(256)
void scan_pass2(const float* __restrict__ Sg, const float* __restrict__ cdg,
                const float* __restrict__ A_log, float* __restrict__ h0g) {
    const int gidx = blockIdx.x * blockDim.x + threadIdx.x;
    const int bh = gidx >> 11, e4 = (gidx & 2047) << 2;
    const int h = bh & 15, b = bh >> 4;
    const float eA = expf(A_log[h]);
    float4 st = make_float4(0.f, 0.f, 0.f, 0.f);
    #pragma unroll
    for (int c = 0; c < 8; c++) {
        size_t base = ((size_t)(bh * 8 + c)) * 8192 + e4;
        *(float4*)&h0g[base] = st;
        float q = expf(-eA * cdg[(size_t)(b * SS + c * L64 + 63) * Hh + h]);
        float4 s4 = *(const float4*)&Sg[base];
        st.x = q * st.x + s4.x;
        st.y = q * st.y + s4.y;
        st.z = q * st.z + s4.z;
        st.w = q * st.w + s4.w;
    }
}

__global__ __launch_bounds__(256, 2)
void scan_pass3(const float* __restrict__ proj, const float* __restrict__ cdg,
                const float* __restrict__ h0g, const float* __restrict__ A_log,
                const float* __restrict__ Dskip, float* __restrict__ gy) {
    const int blk = blockIdx.x;
    const int c = blk & 7, bh = blk >> 3, h = bh & 15, b = bh >> 4;
    const int tid = threadIdx.x;
    const int tok0 = b * SS + c * L64;
    const float eA  = expf(A_log[h]);
    const float dsk = Dskip[h];

    extern __shared__ float sm3[];
    float* Csm  = sm3;
    float* Bsm  = Csm + 64 * 132;
    float* Udsm = Bsm + 64 * 132;
    float* Msm  = Udsm + 64 * 68;
    float* cds  = Msm + 64 * 68;

    if (tid < 64) cds[tid] = cdg[(size_t)(tok0 + tid) * Hh + h];
    for (int i = tid; i < 64 * 32; i += 256) {
        int t = i >> 5, rq = (i & 31) << 2;
        const float* src = &proj[(size_t)(tok0 + t) * NPROJ + 2048 + h * 128 + rq];
        *(float4*)&Bsm[t * 132 + rq] = *(const float4*)src;
        *(float4*)&Csm[t * 132 + rq] = *(const float4*)(src + 2048);
    }
    __syncthreads();
    for (int i = tid; i < 64 * 16; i += 256) {
        int t = i >> 4, pq = (i & 15) << 2;
        float4 uv = *(const float4*)&proj[(size_t)(tok0 + t) * NPROJ + 1024 + h * 64 + pq];
        float dtv = (t == 0) ? cds[0] : (cds[t] - cds[t - 1]);
        float4 o; o.x = uv.x * dtv; o.y = uv.y * dtv; o.z = uv.z * dtv; o.w = uv.w * dtv;
        *(float4*)&Udsm[t * 68 + pq] = o;
    }
    __syncthreads();

    const int t0 = (tid >> 4) * 4;
    const int q0 = (tid & 15) * 4;

    float2 ga[4][4];
    #pragma unroll
    for (int i = 0; i < 4; i++)
        #pragma unroll
        for (int j = 0; j < 4; j++) ga[i][j] = F2(0.f, 0.f);
    for (int k = 0; k < 128; k += 4) {
        float4 cr[4], br[4];
        #pragma unroll
        for (int r = 0; r < 4; r++) {
            cr[r] = *(const float4*)&Csm[(t0 + r) * 132 + k];
            br[r] = *(const float4*)&Bsm[(q0 + r) * 132 + k];
        }
        #pragma unroll
        for (int tt = 0; tt < 4; tt++) {
            float2 c2a = F2(cr[tt].x, cr[tt].y), c2b = F2(cr[tt].z, cr[tt].w);
            #pragma unroll
            for (int qq = 0; qq < 4; qq++) {
                ga[tt][qq] = ffma2(c2a, F2(br[qq].x, br[qq].y), ga[tt][qq]);
                ga[tt][qq] = ffma2(c2b, F2(br[qq].z, br[qq].w), ga[tt][qq]);
            }
        }
    }
    #pragma unroll
    for (int tt = 0; tt < 4; tt++) {
        int t = t0 + tt;
        #pragma unroll
        for (int qq = 0; qq < 4; qq++) {
            int q = q0 + qq;
            float g = ga[tt][qq].x + ga[tt][qq].y;
            float w = (q <= t) ? __expf(-eA * (cds[t] - cds[q])) : 0.f;
            Msm[t * 68 + q] = g * w;
        }
    }
    __syncthreads();

    const float* h0b = &h0g[(size_t)blk * 8192];
    float4 hreg[4];
    #pragma unroll
    for (int j = 0; j < 4; j++) {
        int i = tid + j * 256;
        int rn = i >> 4, pq = (i & 15) << 2;
        hreg[j] = *(const float4*)&h0b[rn * 64 + pq];
    }

    const int p0 = q0;
    float2 ya[4][2], yb[4][2];
    #pragma unroll
    for (int i = 0; i < 4; i++) {
        ya[i][0] = F2(0.f, 0.f); ya[i][1] = F2(0.f, 0.f);
        yb[i][0] = F2(0.f, 0.f); yb[i][1] = F2(0.f, 0.f);
    }
    for (int q = 0; q < 64; q += 4) {
        float4 mr[4], ur[4];
        #pragma unroll
        for (int r = 0; r < 4; r++) mr[r] = *(const float4*)&Msm[(t0 + r) * 68 + q];
        #pragma unroll
        for (int j = 0; j < 4; j++) ur[j] = *(const float4*)&Udsm[(q + j) * 68 + p0];
        #pragma unroll
        for (int tt = 0; tt < 4; tt++) {
            float4 m4 = mr[tt];
            ya[tt][0] = ffma2(F2(m4.x, m4.x), F2(ur[0].x, ur[0].y), ya[tt][0]);
            ya[tt][1] = ffma2(F2(m4.x, m4.x), F2(ur[0].z, ur[0].w), ya[tt][1]);
            ya[tt][0] = ffma2(F2(m4.y, m4.y), F2(ur[1].x, ur[1].y), ya[tt][0]);
            ya[tt][1] = ffma2(F2(m4.y, m4.y), F2(ur[1].z, ur[1].w), ya[tt][1]);
            ya[tt][0] = ffma2(F2(m4.z, m4.z), F2(ur[2].x, ur[2].y), ya[tt][0]);
            ya[tt][1] = ffma2(F2(m4.z, m4.z), F2(ur[2].z, ur[2].w), ya[tt][1]);
            ya[tt][0] = ffma2(F2(m4.w, m4.w), F2(ur[3].x, ur[3].y), ya[tt][0]);
            ya[tt][1] = ffma2(F2(m4.w, m4.w), F2(ur[3].z, ur[3].w), ya[tt][1]);
        }
    }

    float* h0s = Bsm;
    #pragma unroll
    for (int j = 0; j < 4; j++) {
        int i = tid + j * 256;
        int rn = i >> 4, pq = (i & 15) << 2;
        *(float4*)&h0s[rn * 68 + pq] = hreg[j];
    }
    __syncthreads();

    for (int rn = 0; rn < 64; rn += 4) {
        float4 cr[4], hr[4];
        #pragma unroll
        for (int r = 0; r < 4; r++) cr[r] = *(const float4*)&Csm[(t0 + r) * 132 + rn];
        #pragma unroll
        for (int j = 0; j < 4; j++) hr[j] = *(const float4*)&h0s[(rn + j) * 68 + p0];
        #pragma unroll
        for (int tt = 0; tt < 4; tt++) {
            float4 c4 = cr[tt];
            yb[tt][0] = ffma2(F2(c4.x, c4.x), F2(hr[0].x, hr[0].y), yb[tt][0]);
            yb[tt][1] = ffma2(F2(c4.x, c4.x), F2(hr[0].z, hr[0].w), yb[tt][1]);
            yb[tt][0] = ffma2(F2(c4.y, c4.y), F2(hr[1].x, hr[1].y), yb[tt][0]);
            yb[tt][1] = ffma2(F2(c4.y, c4.y), F2(hr[1].z, hr[1].w), yb[tt][1]);
            yb[tt][0] = ffma2(F2(c4.z, c4.z), F2(hr[2].x, hr[2].y), yb[tt][0]);
            yb[tt][1] = ffma2(F2(c4.z, c4.z), F2(hr[2].z, hr[2].w), yb[tt][1]);
            yb[tt][0] = ffma2(F2(c4.w, c4.w), F2(hr[3].x, hr[3].y), yb[tt][0]);
            yb[tt][1] = ffma2(F2(c4.w, c4.w), F2(hr[3].z, hr[3].w), yb[tt][1]);
        }
    }
    __syncthreads();
    #pragma unroll
    for (int j = 0; j < 4; j++) {
        int i = tid + j * 256;
        int rn = i >> 4, pq = (i & 15) << 2;
        *(float4*)&h0s[rn * 68 + pq] = *(const float4*)&h0b[(64 + rn) * 64 + pq];
    }
    __syncthreads();
    for (int rn = 0; rn < 64; rn += 4) {
        float4 cr[4], hr[4];
        #pragma unroll
        for (int r = 0; r < 4; r++) cr[r] = *(const float4*)&Csm[(t0 + r) * 132 + 64 + rn];
        #pragma unroll
        for (int j = 0; j < 4; j++) hr[j] = *(const float4*)&h0s[(rn + j) * 68 + p0];
        #pragma unroll
        for (int tt = 0; tt < 4; tt++) {
            float4 c4 = cr[tt];
            yb[tt][0] = ffma2(F2(c4.x, c4.x), F2(hr[0].x, hr[0].y), yb[tt][0]);
            yb[tt][1] = ffma2(F2(c4.x, c4.x), F2(hr[0].z, hr[0].w), yb[tt][1]);
            yb[tt][0] = ffma2(F2(c4.y, c4.y), F2(hr[1].x, hr[1].y), yb[tt][0]);
            yb[tt][1] = ffma2(F2(c4.y, c4.y), F2(hr[1].z, hr[1].w), yb[tt][1]);
            yb[tt][0] = ffma2(F2(c4.z, c4.z), F2(hr[2].x, hr[2].y), yb[tt][0]);
            yb[tt][1] = ffma2(F2(c4.z, c4.z), F2(hr[2].z, hr[2].w), yb[tt][1]);
            yb[tt][0] = ffma2(F2(c4.w, c4.w), F2(hr[3].x, hr[3].y), yb[tt][0]);
            yb[tt][1] = ffma2(F2(c4.w, c4.w), F2(hr[3].z, hr[3].w), yb[tt][1]);
        }
    }

    #pragma unroll
    for (int tt = 0; tt < 4; tt++) {
        int t = t0 + tt;
        float Qt = __expf(-eA * cds[t]);
        size_t token = (size_t)(tok0 + t);
        float4 uv = *(const float4*)&proj[token * NPROJ + 1024 + h * 64 + p0];
        float4 zv = *(const float4*)&proj[token * NPROJ + h * 64 + p0];
        float y0 = ya[tt][0].x + Qt * yb[tt][0].x;
        float y1 = ya[tt][0].y + Qt * yb[tt][0].y;
        float y2 = ya[tt][1].x + Qt * yb[tt][1].x;
        float y3 = ya[tt][1].y + Qt * yb[tt][1].y;
        float4 o;
        o.x = rnd_tf32((y0 + uv.x * dsk) * (zv.x / (1.f + expf(-zv.x))));
        o.y = rnd_tf32((y1 + uv.y * dsk) * (zv.y / (1.f + expf(-zv.y))));
        o.z = rnd_tf32((y2 + uv.z * dsk) * (zv.z / (1.f + expf(-zv.z))));
        o.w = rnd_tf32((y3 + uv.w * dsk) * (zv.w / (1.f + expf(-zv.w))));
        *(float4*)&gy[token * DIN + h * 64 + p0] = o;
    }
}

// ---------------- launch ----------------
extern "C" void kernel_launch(void* const* d_in, const int* in_sizes, int n_in,
                              void* d_out, int out_size) {
    const float* x      = (const float*)d_in[0];
    const float* mask   = (const float*)d_in[1];
    const float* n1w    = (const float*)d_in[2];
    const float* n2w    = (const float*)d_in[3];
    const float* Wz     = (const float*)d_in[4];
    const float* Wx     = (const float*)d_in[5];
    const float* Wb     = (const float*)d_in[6];
    const float* Wc     = (const float*)d_in[7];
    const float* Wdt    = (const float*)d_in[8];
    const float* dtb    = (const float*)d_in[9];
    const float* A_log  = (const float*)d_in[10];
    const float* D_skip = (const float*)d_in[11];
    const float* Wout   = (const float*)d_in[12];
    const float* w1     = (const float*)d_in[13];
    const float* w2     = (const float*)d_in[14];
    const float* w3     = (const float*)d_in[15];
    float* out = (float*)d_out;

    float *xn, *proj, *gy, *x1, *xn2, *g2;
    float *WpT, *W13T, *WoT, *W2T, *Sg, *h0g, *cdg;
    cudaGetSymbolAddress((void**)&xn,   g_xn);
    cudaGetSymbolAddress((void**)&proj, g_proj);
    cudaGetSymbolAddress((void**)&gy,   g_gy);
    cudaGetSymbolAddress((void**)&x1,   g_x1);
    cudaGetSymbolAddress((void**)&xn2,  g_xn2);
    cudaGetSymbolAddress((void**)&g2,   g_g2);
    cudaGetSymbolAddress((void**)&WpT,  g_WpT);
    cudaGetSymbolAddress((void**)&W13T, g_W13T);
    cudaGetSymbolAddress((void**)&WoT,  g_WoT);
    cudaGetSymbolAddress((void**)&W2T,  g_W2T);
    cudaGetSymbolAddress((void**)&Sg,   g_S);
    cudaGetSymbolAddress((void**)&h0g,  g_h0);
    cudaGetSymbolAddress((void**)&cdg,  g_cd);

    const int smemMain = NSTAGE * (ASZ + BSZ) * 4;       // 110,592
    const int smemSk   = NSTAGE * (ASZK + BSZK) * 4;     // 55,296
    const int smemP1   = (128 + 64 * 132 + 64 * 68) * 4;
    const int smemP3   = (64 * 132 * 2 + 64 * 68 * 2 + 64) * 4;
    static int configured = 0;
    if (!configured) {
        cudaFuncSetAttribute(mma_gemm,    cudaFuncAttributeMaxDynamicSharedMemorySize, smemMain);
        cudaFuncSetAttribute(mma_gemm_sk, cudaFuncAttributeMaxDynamicSharedMemorySize, smemSk);
        cudaFuncSetAttribute(scan_pass1,  cudaFuncAttributeMaxDynamicSharedMemorySize, smemP1);
        cudaFuncSetAttribute(scan_pass3,  cudaFuncAttributeMaxDynamicSharedMemorySize, smemP3);
        configured = 1;
    }

    tpack_kernel<<<dim3(196 + N13/32, 16), 256>>>(Wz, Wx, Wb, Wc, Wdt, w1, w3);
    tpack_sk_kernel<<<dim3(32, 44), 256>>>(Wout, w2);
    rmsnorm_kernel<<<TT/2, 256>>>(x, n1w, mask, xn, 1);

    mma_gemm<<<dim3(NPROJ/128, TT/128), 256, smemMain>>>(xn, WpT, proj, TT, NPROJ, Dm, 0, nullptr, nullptr);

    scan_pass1<<<NCHK, 256, smemP1>>>(proj, dtb, A_log, Sg, cdg);
    scan_pass2<<<512, 256>>>(Sg, cdg, A_log, h0g);
    scan_pass3<<<NCHK, 256, smemP3>>>(proj, cdg, h0g, A_log, D_skip, gy);

    mma_gemm_sk<<<dim3(Dm/64, TT/64), 256, smemSk>>>(gy, WoT, x1, TT, Dm, DIN, 1, x, mask);
    rmsnorm_kernel<<<TT/2, 256>>>(x1, n2w, mask, xn2, 0);

    // w1/w3 interleaved GEMM with fused swiglu epilogue -> g2 directly
    mma_gemm<<<dim3(N13/128, TT/128), 256, smemMain>>>(xn2, W13T, g2, TT, N13, Dm, 5, nullptr, nullptr);
    mma_gemm_sk<<<dim3(Dm/64, TT/64), 256, smemSk>>>(g2, W2T, out, TT, Dm, DFFP, 2, x1, mask);
}

// round 16
// speedup vs baseline: 1.0549x; 1.0054x over previous
#include <cuda_runtime.h>
#include <math.h>
#include <stdint.h>

// ---------------- problem constants ----------------
#define Dm     512
#define DIN    1024
#define Hh     16
#define DFF    1368
#define DFFP   1408
#define N13    2816            // w1/w3 column-interleaved (2*1368 | pad)
#define NPROJ  6272            // Wz|Wx|Wb|Wc|Wdt(pad)
#define DTC    6144
#define BB     4
#define SS     512
#define TT     2048
#define NCHK   512
#define L64    64

// ---------------- static scratch ----------------
__device__ __align__(16) float g_xn  [TT*Dm];
__device__ __align__(16) float g_proj[TT*NPROJ];
__device__ __align__(16) float g_gy  [TT*DIN];
__device__ __align__(16) float g_x1  [TT*Dm];
__device__ __align__(16) float g_xn2 [TT*Dm];
__device__ __align__(16) float g_g2  [TT*DFFP];
__device__ __align__(16) float g_WpT [NPROJ*Dm];   // [n][k]
__device__ __align__(16) float g_W13T[N13*Dm];     // [n][k], n interleaved w1/w3
__device__ __align__(16) float g_WoT [Dm*DIN];
__device__ __align__(16) float g_W2T [Dm*DFFP];
__device__ __align__(16) float g_S   [NCHK*8192];
__device__ __align__(16) float g_cd  [TT*Hh];

// ---------------- helpers ----------------
__device__ __forceinline__ uint32_t f2tf32(float v) {
    uint32_t u; asm("cvt.rna.tf32.f32 %0, %1;" : "=r"(u) : "f"(v)); return u;
}
__device__ __forceinline__ float rnd_tf32(float v) { return __uint_as_float(f2tf32(v)); }

#define CP16(dst, src) asm volatile("cp.async.cg.shared.global [%0], [%1], 16;\n" :: "r"(dst), "l"(src))
#define CP_COMMIT()    asm volatile("cp.async.commit_group;\n")
#define CP_WAIT(n)     asm volatile("cp.async.wait_group %0;\n" :: "n"(n))

__device__ __forceinline__ void mma_tf32(float* c, const uint32_t* a, const uint32_t* b) {
    asm volatile("mma.sync.aligned.m16n8k8.row.col.f32.tf32.tf32.f32 "
        "{%0,%1,%2,%3}, {%4,%5,%6,%7}, {%8,%9}, {%0,%1,%2,%3};"
        : "+f"(c[0]), "+f"(c[1]), "+f"(c[2]), "+f"(c[3])
        : "r"(a[0]), "r"(a[1]), "r"(a[2]), "r"(a[3]), "r"(b[0]), "r"(b[1]));
}
__device__ __forceinline__ void ldsm_x4(uint32_t& r0, uint32_t& r1, uint32_t& r2, uint32_t& r3,
                                        uint32_t addr) {
    asm volatile("ldmatrix.sync.aligned.m8n8.x4.shared.b16 {%0,%1,%2,%3}, [%4];"
        : "=r"(r0), "=r"(r1), "=r"(r2), "=r"(r3) : "r"(addr));
}
__device__ __forceinline__ float2 ffma2(float2 a, float2 b, float2 c) {
    unsigned long long A = *reinterpret_cast<unsigned long long*>(&a);
    unsigned long long B = *reinterpret_cast<unsigned long long*>(&b);
    unsigned long long C = *reinterpret_cast<unsigned long long*>(&c);
    unsigned long long D;
    asm("fma.rn.f32x2 %0, %1, %2, %3;" : "=l"(D) : "l"(A), "l"(B), "l"(C));
    return *reinterpret_cast<float2*>(&D);
}
#define F2(a,b) make_float2((a),(b))

// ---------------- transposed pack: Wp | W13 (w1/w3 interleaved) ----------------
__global__ __launch_bounds__(256)
void tpack_kernel(const float* __restrict__ Wz, const float* __restrict__ Wx,
                  const float* __restrict__ Wb, const float* __restrict__ Wc,
                  const float* __restrict__ Wdt,
                  const float* __restrict__ w1, const float* __restrict__ w3) {
    __shared__ float tile[32][33];
    const int bx = blockIdx.x, by = blockIdx.y;
    const int tx = threadIdx.x & 31, ty = threadIdx.x >> 5;
    const int r0 = by * 32;
    int mat, c0;
    if (bx < 196) { mat = 0; c0 = bx * 32; }
    else          { mat = 1; c0 = (bx - 196) * 32; }

    #pragma unroll
    for (int i = 0; i < 32; i += 8) {
        int r = r0 + ty + i, c = c0 + tx;
        float v;
        if (mat == 0) {
            if      (c < 1024) v = Wz[r * 1024 + c];
            else if (c < 2048) v = Wx[r * 1024 + c - 1024];
            else if (c < 4096) v = Wb[r * 2048 + c - 2048];
            else if (c < 6144) v = Wc[r * 2048 + c - 4096];
            else if (c < 6160) v = Wdt[r * 16 + c - 6144];
            else               v = 0.f;
        } else {
            v = 0.f;
            if (c < 2 * DFF) {
                const float* w = (c & 1) ? w3 : w1;
                v = w[r * DFF + (c >> 1)];
            }
        }
        tile[ty + i][tx] = v;
    }
    __syncthreads();
    float* out = (mat == 0) ? g_WpT : g_W13T;
    #pragma unroll
    for (int i = 0; i < 32; i += 8)
        out[(size_t)(c0 + ty + i) * Dm + r0 + tx] = rnd_tf32(tile[tx][ty + i]);
}

// ---------------- transposed pack: Wout, w2 ----------------
__global__ __launch_bounds__(256)
void tpack_sk_kernel(const float* __restrict__ Wout, const float* __restrict__ w2) {
    __shared__ float tile[32][33];
    const int bx = blockIdx.x, by = blockIdx.y;
    const int tx = threadIdx.x & 31, ty = threadIdx.x >> 5;
    const int mat = (bx < 16) ? 0 : 1;
    const int c0 = ((mat == 0) ? bx : bx - 16) * 32;
    const int r0 = by * 32;
    if (mat == 0 && r0 >= DIN) return;

    #pragma unroll
    for (int i = 0; i < 32; i += 8) {
        int r = r0 + ty + i, c = c0 + tx;
        float v;
        if (mat == 0) v = Wout[(size_t)r * 512 + c];
        else          v = (r < DFF) ? w2[(size_t)r * 512 + c] : 0.f;
        tile[ty + i][tx] = v;
    }
    __syncthreads();
    float* out = mat ? g_W2T : g_WoT;
    const int ld = mat ? DFFP : DIN;
    #pragma unroll
    for (int i = 0; i < 32; i += 8)
        out[(size_t)(c0 + ty + i) * ld + r0 + tx] = rnd_tf32(tile[tx][ty + i]);
}

// ---------------- rmsnorm: 2 tokens per block ----------------
__global__ __launch_bounds__(256)
void rmsnorm_kernel(const float* __restrict__ x, const float* __restrict__ w,
                    const float* __restrict__ mask, float* __restrict__ out, int useMask) {
    const int half = threadIdx.x >> 7;
    const int li   = threadIdx.x & 127;
    const int t    = blockIdx.x * 2 + half;
    const float4* xr = (const float4*)(x + (size_t)t * Dm);
    float4 v = xr[li];
    float s = v.x * v.x + v.y * v.y + v.z * v.z + v.w * v.w;
    __shared__ float red[8];
    #pragma unroll
    for (int o = 16; o; o >>= 1) s += __shfl_down_sync(0xFFFFFFFFu, s, o);
    if ((threadIdx.x & 31) == 0) red[threadIdx.x >> 5] = s;
    __syncthreads();
    const float* rh = red + half * 4;
    float tot = rh[0] + rh[1] + rh[2] + rh[3];
    float inv = rsqrtf(tot / (float)Dm + 1e-6f);
    float m = useMask ? mask[t] : 1.f;
    inv *= m;
    float4 wv = ((const float4*)w)[li];
    float4 o;
    o.x = rnd_tf32(v.x * inv * wv.x);
    o.y = rnd_tf32(v.y * inv * wv.y);
    o.z = rnd_tf32(v.z * inv * wv.z);
    o.w = rnd_tf32(v.w * inv * wv.w);
    ((float4*)(out + (size_t)t * Dm))[li] = o;
}

// ---------------- tf32 GEMM, 128x128, 256 threads (8 warps 4x2), ldmatrix ----------------
// mode 0: C=acc   1: C=res+acc*mask[row]   2: C=(res+acc)*mask
// mode 5: fused swiglu (interleaved w1/w3 cols), output stride N/2
#define NSTAGE 3
#define ASZ (128*36)
#define BSZ (128*36)
__global__ __launch_bounds__(256, 2)
void mma_gemm(const float* __restrict__ A, const float* __restrict__ BT,
              float* __restrict__ C, int M, int N, int K,
              int mode, const float* __restrict__ res, const float* __restrict__ mask) {
    extern __shared__ uint32_t smem[];
    uint32_t* Asm = smem;
    uint32_t* Bsm = smem + NSTAGE * ASZ;
    const uint32_t as_sh = (uint32_t)__cvta_generic_to_shared(Asm);
    const uint32_t bs_sh = (uint32_t)__cvta_generic_to_shared(Bsm);

    const int bm = blockIdx.y * 128, bn = blockIdx.x * 128;
    const int tid = threadIdx.x;
    const int lane = tid & 31, w = tid >> 5;
    const int wm = (w >> 1) * 32, wn = (w & 1) * 64;
    const int g = lane >> 2, tg = lane & 3;
    const int kIter = K >> 5;

    const int am0 = tid >> 3, akq = (tid & 7) * 4;

    auto issue = [&](int it) {
        const int st = it % NSTAGE;
        const int k0 = it << 5;
        #pragma unroll
        for (int i = 0; i < 4; i++) {
            int m = am0 + i * 32;
            CP16(as_sh + (st * ASZ + m * 36 + akq) * 4,
                 A + (size_t)(bm + m) * K + k0 + akq);
        }
        #pragma unroll
        for (int i = 0; i < 4; i++) {
            int n = am0 + i * 32;
            CP16(bs_sh + (st * BSZ + n * 36 + akq) * 4,
                 BT + (size_t)(bn + n) * K + k0 + akq);
        }
        CP_COMMIT();
    };

    const int tq = lane & 7, sel = lane >> 3;
    uint32_t aBase[2], bBase[4];
    #pragma unroll
    for (int mt = 0; mt < 2; mt++)
        aBase[mt] = as_sh + (((wm + mt * 16 + (sel & 1) * 8 + tq) * 36 + (sel >> 1) * 4) << 2);
    #pragma unroll
    for (int j = 0; j < 4; j++)
        bBase[j] = bs_sh + (((wn + j * 16 + (sel >> 1) * 8 + tq) * 36 + (sel & 1) * 4) << 2);

    float acc[2][8][4];
    #pragma unroll
    for (int mt = 0; mt < 2; mt++)
        #pragma unroll
        for (int nt = 0; nt < 8; nt++)
            #pragma unroll
            for (int q = 0; q < 4; q++) acc[mt][nt][q] = 0.f;

    issue(0); issue(1);

    for (int it = 0; it < kIter; it++) {
        if (it == kIter - 1) { CP_WAIT(0); } else { CP_WAIT(1); }
        __syncthreads();
        if (it + 2 < kIter) issue(it + 2);

        const uint32_t soA = (uint32_t)((it % NSTAGE) * ASZ) << 2;
        const uint32_t soB = (uint32_t)((it % NSTAGE) * BSZ) << 2;
        #pragma unroll
        for (int kh = 0; kh < 4; kh++) {
            const uint32_t kbb = (uint32_t)(kh * 8) << 2;
            uint32_t af[2][4];
            ldsm_x4(af[0][0], af[0][1], af[0][2], af[0][3], aBase[0] + soA + kbb);
            ldsm_x4(af[1][0], af[1][1], af[1][2], af[1][3], aBase[1] + soA + kbb);
            #pragma unroll
            for (int j = 0; j < 4; j++) {
                uint32_t b0, b1, b2, b3;
                ldsm_x4(b0, b1, b2, b3, bBase[j] + soB + kbb);
                uint32_t bf0[2] = {b0, b1};
                uint32_t bf1[2] = {b2, b3};
                mma_tf32(acc[0][2 * j],     af[0], bf0);
                mma_tf32(acc[1][2 * j],     af[1], bf0);
                mma_tf32(acc[0][2 * j + 1], af[0], bf1);
                mma_tf32(acc[1][2 * j + 1], af[1], bf1);
            }
        }
    }

    if (mode == 5) {
        const int halfN = N >> 1;
        #pragma unroll
        for (int mt = 0; mt < 2; mt++) {
            #pragma unroll
            for (int nt = 0; nt < 8; nt++) {
                int r0 = bm + wm + mt * 16 + g;
                int c0 = bn + wn + nt * 8 + tg * 2;      // even
                #pragma unroll
                for (int half = 0; half < 2; half++) {
                    int r = r0 + half * 8;
                    float v0 = acc[mt][nt][half * 2 + 0];   // w1 col
                    float v1 = acc[mt][nt][half * 2 + 1];   // w3 col
                    float sv = v0 / (1.f + expf(-v0));
                    C[(size_t)r * halfN + (c0 >> 1)] = rnd_tf32(sv * v1);
                }
            }
        }
        return;
    }

    #pragma unroll
    for (int mt = 0; mt < 2; mt++) {
        #pragma unroll
        for (int nt = 0; nt < 8; nt++) {
            int r0 = bm + wm + mt * 16 + g;
            int c0 = bn + wn + nt * 8 + tg * 2;
            #pragma unroll
            for (int half = 0; half < 2; half++) {
                int r = r0 + half * 8;
                float mk = (mode == 1 || mode == 2) ? mask[r] : 0.f;
                #pragma unroll
                for (int q = 0; q < 2; q++) {
                    int c = c0 + q;
                    float v = acc[mt][nt][half * 2 + q];
                    size_t idx = (size_t)r * N + c;
                    float o;
                    if (mode == 0)      o = v;
                    else if (mode == 1) o = res[idx] + v * mk;
                    else                o = (res[idx] + v) * mk;
                    C[idx] = o;
                }
            }
        }
    }
}

// ---------------- tf32 GEMM, 64x64 tile, ldmatrix (skinny: Wout, w2) ----------------
#define ASZK (64*36)
#define BSZK (64*36)
__global__ __launch_bounds__(256, 3)
void mma_gemm_sk(const float* __restrict__ A, const float* __restrict__ BT,
                 float* __restrict__ C, int M, int N, int K,
                 int mode, const float* __restrict__ res, const float* __restrict__ mask) {
    extern __shared__ uint32_t smem[];
    uint32_t* Asm = smem;
    uint32_t* Bsm = smem + NSTAGE * ASZK;
    const uint32_t as_sh = (uint32_t)__cvta_generic_to_shared(Asm);
    const uint32_t bs_sh = (uint32_t)__cvta_generic_to_shared(Bsm);

    const int bm = blockIdx.y * 64, bn = blockIdx.x * 64;
    const int tid = threadIdx.x;
    const int lane = tid & 31, w = tid >> 5;
    const int wm = (w & 1) * 32, wn = (w >> 1) * 16;
    const int g = lane >> 2, tg = lane & 3;
    const int kIter = K >> 5;

    const int am0 = tid >> 3, akq = (tid & 7) * 4;

    auto issue = [&](int it) {
        const int st = it % NSTAGE;
        const int k0 = it << 5;
        #pragma unroll
        for (int i = 0; i < 2; i++) {
            int m = am0 + i * 32;
            CP16(as_sh + (st * ASZK + m * 36 + akq) * 4,
                 A + (size_t)(bm + m) * K + k0 + akq);
        }
        #pragma unroll
        for (int i = 0; i < 2; i++) {
            int n = am0 + i * 32;
            CP16(bs_sh + (st * BSZK + n * 36 + akq) * 4,
                 BT + (size_t)(bn + n) * K + k0 + akq);
        }
        CP_COMMIT();
    };

    const int tq = lane & 7, sel = lane >> 3;
    uint32_t aBase[2], bBase;
    #pragma unroll
    for (int mt = 0; mt < 2; mt++)
        aBase[mt] = as_sh + (((wm + mt * 16 + (sel & 1) * 8 + tq) * 36 + (sel >> 1) * 4) << 2);
    bBase = bs_sh + (((wn + (sel >> 1) * 8 + tq) * 36 + (sel & 1) * 4) << 2);

    float acc[2][2][4];
    #pragma unroll
    for (int mt = 0; mt < 2; mt++)
        #pragma unroll
        for (int nt = 0; nt < 2; nt++)
            #pragma unroll
            for (int q = 0; q < 4; q++) acc[mt][nt][q] = 0.f;

    issue(0); issue(1);

    for (int it = 0; it < kIter; it++) {
        if (it == kIter - 1) { CP_WAIT(0); } else { CP_WAIT(1); }
        __syncthreads();
        if (it + 2 < kIter) issue(it + 2);

        const uint32_t soA = (uint32_t)((it % NSTAGE) * ASZK) << 2;
        const uint32_t soB = (uint32_t)((it % NSTAGE) * BSZK) << 2;
        #pragma unroll
        for (int kh = 0; kh < 4; kh++) {
            const uint32_t kbb = (uint32_t)(kh * 8) << 2;
            uint32_t af[2][4];
            ldsm_x4(af[0][0], af[0][1], af[0][2], af[0][3], aBase[0] + soA + kbb);
            ldsm_x4(af[1][0], af[1][1], af[1][2], af[1][3], aBase[1] + soA + kbb);
            uint32_t b0, b1, b2, b3;
            ldsm_x4(b0, b1, b2, b3, bBase + soB + kbb);
            uint32_t bf0[2] = {b0, b1};
            uint32_t bf1[2] = {b2, b3};
            mma_tf32(acc[0][0], af[0], bf0);
            mma_tf32(acc[1][0], af[1], bf0);
            mma_tf32(acc[0][1], af[0], bf1);
            mma_tf32(acc[1][1], af[1], bf1);
        }
    }

    #pragma unroll
    for (int mt = 0; mt < 2; mt++) {
        #pragma unroll
        for (int nt = 0; nt < 2; nt++) {
            int r0 = bm + wm + mt * 16 + g;
            int c0 = bn + wn + nt * 8 + tg * 2;
            #pragma unroll
            for (int half = 0; half < 2; half++) {
                int r = r0 + half * 8;
                float mk = (mode == 1 || mode == 2) ? mask[r] : 0.f;
                #pragma unroll
                for (int q = 0; q < 2; q++) {
                    int c = c0 + q;
                    float v = acc[mt][nt][half * 2 + q];
                    size_t idx = (size_t)r * N + c;
                    float o;
                    if (mode == 0)      o = v;
                    else if (mode == 1) o = res[idx] + v * mk;
                    else                o = (res[idx] + v) * mk;
                    C[idx] = o;
                }
            }
        }
    }
}

// ================= chunked SSM scan =================
// Pass 1: per-(b,h,chunk): cumsum(dt) -> cd; S = sum_t w_t * B_t (outer) ud_t
__global__ __launch_bounds__(256, 2)
void scan_pass1(const float* __restrict__ proj, const float* __restrict__ dtb,
                const float* __restrict__ A_log,
                float* __restrict__ Sg, float* __restrict__ cdg) {
    const int blk = blockIdx.x;
    const int c = blk & 7, bh = blk >> 3, h = bh & 15, b = bh >> 4;
    const int tid = threadIdx.x;
    const int tok0 = b * SS + c * L64;

    extern __shared__ float sm1[];
    float* cds = sm1;
    float* wts = sm1 + 64;
    float* Bw  = sm1 + 128;
    float* Ud  = Bw + 64 * 132;

    const float eA = expf(A_log[h]);

    if (tid < 64) {
        float raw = proj[(size_t)(tok0 + tid) * NPROJ + DTC + h] + dtb[h];
        cds[tid] = (raw > 20.f) ? raw : log1pf(expf(raw));
    }
    __syncthreads();
    #pragma unroll
    for (int off = 1; off < 64; off <<= 1) {
        float v = (tid < 64 && tid >= off) ? cds[tid - off] : 0.f;
        __syncthreads();
        if (tid < 64) cds[tid] += v;
        __syncthreads();
    }
    if (tid < 64) {
        cdg[(size_t)(tok0 + tid) * Hh + h] = cds[tid];
        wts[tid] = expf(-eA * (cds[63] - cds[tid]));
    }
    __syncthreads();

    for (int i = tid; i < 64 * 32; i += 256) {
        int t = i >> 5, rq = (i & 31) << 2;
        float4 bv = *(const float4*)&proj[(size_t)(tok0 + t) * NPROJ + 2048 + h * 128 + rq];
        float w = wts[t];
        float4 o; o.x = bv.x * w; o.y = bv.y * w; o.z = bv.z * w; o.w = bv.w * w;
        *(float4*)&Bw[t * 132 + rq] = o;
    }
    for (int i = tid; i < 64 * 16; i += 256) {
        int t = i >> 4, pq = (i & 15) << 2;
        float4 uv = *(const float4*)&proj[(size_t)(tok0 + t) * NPROJ + 1024 + h * 64 + pq];
        float dtv = (t == 0) ? cds[0] : (cds[t] - cds[t - 1]);
        float4 o; o.x = uv.x * dtv; o.y = uv.y * dtv; o.z = uv.z * dtv; o.w = uv.w * dtv;
        *(float4*)&Ud[t * 68 + pq] = o;
    }
    __syncthreads();

    const int rn0 = (tid >> 3) * 4, p0 = (tid & 7) * 8;
    float2 acc[4][4];
    #pragma unroll
    for (int r = 0; r < 4; r++)
        #pragma unroll
        for (int j = 0; j < 4; j++) acc[r][j] = F2(0.f, 0.f);

    for (int t = 0; t < 64; t++) {
        float4 bb = *(const float4*)&Bw[t * 132 + rn0];
        float4 u0 = *(const float4*)&Ud[t * 68 + p0];
        float4 u1 = *(const float4*)&Ud[t * 68 + p0 + 4];
        float br[4] = {bb.x, bb.y, bb.z, bb.w};
        float2 ua = F2(u0.x, u0.y), ub = F2(u0.z, u0.w);
        float2 uc = F2(u1.x, u1.y), ue = F2(u1.z, u1.w);
        #pragma unroll
        for (int r = 0; r < 4; r++) {
            float2 b2 = F2(br[r], br[r]);
            acc[r][0] = ffma2(b2, ua, acc[r][0]);
            acc[r][1] = ffma2(b2, ub, acc[r][1]);
            acc[r][2] = ffma2(b2, uc, acc[r][2]);
            acc[r][3] = ffma2(b2, ue, acc[r][3]);
        }
    }
    float* Sb = Sg + (size_t)blk * 8192;
    #pragma unroll
    for (int r = 0; r < 4; r++) {
        float4 o0; o0.x = acc[r][0].x; o0.y = acc[r][0].y; o0.z = acc[r][1].x; o0.w = acc[r][1].y;
        float4 o1; o1.x = acc[r][2].x; o1.y = acc[r][2].y; o1.z = acc[r][3].x; o1.w = acc[r][3].y;
        *(float4*)&Sb[(rn0 + r) * 64 + p0]     = o0;
        *(float4*)&Sb[(rn0 + r) * 64 + p0 + 4] = o1;
    }
}

// Pass 3 (now with inline chunk recurrence; pass2 eliminated):
// h0(c) computed from Sg with the exact pass2 FP order: h = q_j*h + S_j, j=0..c-1.
__global__ __launch_bounds__(256, 2)
void scan_pass3(const float* __restrict__ proj, const float* __restrict__ cdg,
                const float* __restrict__ Sg, const float* __restrict__ A_log,
                const float* __restrict__ Dskip, float* __restrict__ gy) {
    const int blk = blockIdx.x;
    const int c = blk & 7, bh = blk >> 3, h = bh & 15, b = bh >> 4;
    const int tid = threadIdx.x;
    const int tok0 = b * SS + c * L64;
    const float eA  = expf(A_log[h]);
    const float dsk = Dskip[h];

    extern __shared__ float sm3[];
    float* Csm  = sm3;
    float* Bsm  = Csm + 64 * 132;
    float* Udsm = Bsm + 64 * 132;
    float* Msm  = Udsm + 64 * 68;
    float* cds  = Msm + 64 * 68;

    if (tid < 64) cds[tid] = cdg[(size_t)(tok0 + tid) * Hh + h];
    for (int i = tid; i < 64 * 32; i += 256) {
        int t = i >> 5, rq = (i & 31) << 2;
        const float* src = &proj[(size_t)(tok0 + t) * NPROJ + 2048 + h * 128 + rq];
        *(float4*)&Bsm[t * 132 + rq] = *(const float4*)src;
        *(float4*)&Csm[t * 132 + rq] = *(const float4*)(src + 2048);
    }
    __syncthreads();
    for (int i = tid; i < 64 * 16; i += 256) {
        int t = i >> 4, pq = (i & 15) << 2;
        float4 uv = *(const float4*)&proj[(size_t)(tok0 + t) * NPROJ + 1024 + h * 64 + pq];
        float dtv = (t == 0) ? cds[0] : (cds[t] - cds[t - 1]);
        float4 o; o.x = uv.x * dtv; o.y = uv.y * dtv; o.z = uv.z * dtv; o.w = uv.w * dtv;
        *(float4*)&Udsm[t * 68 + pq] = o;
    }
    __syncthreads();

    const int t0 = (tid >> 4) * 4;
    const int q0 = (tid & 15) * 4;

    float2 ga[4][4];
    #pragma unroll
    for (int i = 0; i < 4; i++)
        #pragma unroll
        for (int j = 0; j < 4; j++) ga[i][j] = F2(0.f, 0.f);
    for (int k = 0; k < 128; k += 4) {
        float4 cr[4], br[4];
        #pragma unroll
        for (int r = 0; r < 4; r++) {
            cr[r] = *(const float4*)&Csm[(t0 + r) * 132 + k];
            br[r] = *(const float4*)&Bsm[(q0 + r) * 132 + k];
        }
        #pragma unroll
        for (int tt = 0; tt < 4; tt++) {
            float2 c2a = F2(cr[tt].x, cr[tt].y), c2b = F2(cr[tt].z, cr[tt].w);
            #pragma unroll
            for (int qq = 0; qq < 4; qq++) {
                ga[tt][qq] = ffma2(c2a, F2(br[qq].x, br[qq].y), ga[tt][qq]);
                ga[tt][qq] = ffma2(c2b, F2(br[qq].z, br[qq].w), ga[tt][qq]);
            }
        }
    }
    #pragma unroll
    for (int tt = 0; tt < 4; tt++) {
        int t = t0 + tt;
        #pragma unroll
        for (int qq = 0; qq < 4; qq++) {
            int q = q0 + qq;
            float g = ga[tt][qq].x + ga[tt][qq].y;
            float w = (q <= t) ? __expf(-eA * (cds[t] - cds[q])) : 0.f;
            Msm[t * 68 + q] = g * w;
        }
    }
    __syncthreads();

    // ---- inline chunk recurrence: h0 half0 (rows 0..63) into hreg ----
    const float* Sbase = Sg + (size_t)(bh * 8) * 8192;
    float4 hreg[4];
    #pragma unroll
    for (int jj = 0; jj < 4; jj++) hreg[jj] = make_float4(0.f, 0.f, 0.f, 0.f);
    for (int j = 0; j < c; j++) {
        float q = expf(-eA * cdg[(size_t)(b * SS + j * L64 + 63) * Hh + h]);
        const float* Sb = Sbase + (size_t)j * 8192;
        #pragma unroll
        for (int jj = 0; jj < 4; jj++) {
            int i = tid + jj * 256;
            int rn = i >> 4, pq = (i & 15) << 2;
            float4 s4 = *(const float4*)&Sb[rn * 64 + pq];
            hreg[jj].x = q * hreg[jj].x + s4.x;
            hreg[jj].y = q * hreg[jj].y + s4.y;
            hreg[jj].z = q * hreg[jj].z + s4.z;
            hreg[jj].w = q * hreg[jj].w + s4.w;
        }
    }

    const int p0 = q0;
    float2 ya[4][2], yb[4][2];
    #pragma unroll
    for (int i = 0; i < 4; i++) {
        ya[i][0] = F2(0.f, 0.f); ya[i][1] = F2(0.f, 0.f);
        yb[i][0] = F2(0.f, 0.f); yb[i][1] = F2(0.f, 0.f);
    }
    for (int q = 0; q < 64; q += 4) {
        float4 mr[4], ur[4];
        #pragma unroll
        for (int r = 0; r < 4; r++) mr[r] = *(const float4*)&Msm[(t0 + r) * 68 + q];
        #pragma unroll
        for (int j = 0; j < 4; j++) ur[j] = *(const float4*)&Udsm[(q + j) * 68 + p0];
        #pragma unroll
        for (int tt = 0; tt < 4; tt++) {
            float4 m4 = mr[tt];
            ya[tt][0] = ffma2(F2(m4.x, m4.x), F2(ur[0].x, ur[0].y), ya[tt][0]);
            ya[tt][1] = ffma2(F2(m4.x, m4.x), F2(ur[0].z, ur[0].w), ya[tt][1]);
            ya[tt][0] = ffma2(F2(m4.y, m4.y), F2(ur[1].x, ur[1].y), ya[tt][0]);
            ya[tt][1] = ffma2(F2(m4.y, m4.y), F2(ur[1].z, ur[1].w), ya[tt][1]);
            ya[tt][0] = ffma2(F2(m4.z, m4.z), F2(ur[2].x, ur[2].y), ya[tt][0]);
            ya[tt][1] = ffma2(F2(m4.z, m4.z), F2(ur[2].z, ur[2].w), ya[tt][1]);
            ya[tt][0] = ffma2(F2(m4.w, m4.w), F2(ur[3].x, ur[3].y), ya[tt][0]);
            ya[tt][1] = ffma2(F2(m4.w, m4.w), F2(ur[3].z, ur[3].w), ya[tt][1]);
        }
    }

    float* h0s = Bsm;
    #pragma unroll
    for (int jj = 0; jj < 4; jj++) {
        int i = tid + jj * 256;
        int rn = i >> 4, pq = (i & 15) << 2;
        *(float4*)&h0s[rn * 68 + pq] = hreg[jj];
    }
    __syncthreads();

    for (int rn = 0; rn < 64; rn += 4) {
        float4 cr[4], hr[4];
        #pragma unroll
        for (int r = 0; r < 4; r++) cr[r] = *(const float4*)&Csm[(t0 + r) * 132 + rn];
        #pragma unroll
        for (int j = 0; j < 4; j++) hr[j] = *(const float4*)&h0s[(rn + j) * 68 + p0];
        #pragma unroll
        for (int tt = 0; tt < 4; tt++) {
            float4 c4 = cr[tt];
            yb[tt][0] = ffma2(F2(c4.x, c4.x), F2(hr[0].x, hr[0].y), yb[tt][0]);
            yb[tt][1] = ffma2(F2(c4.x, c4.x), F2(hr[0].z, hr[0].w), yb[tt][1]);
            yb[tt][0] = ffma2(F2(c4.y, c4.y), F2(hr[1].x, hr[1].y), yb[tt][0]);
            yb[tt][1] = ffma2(F2(c4.y, c4.y), F2(hr[1].z, hr[1].w), yb[tt][1]);
            yb[tt][0] = ffma2(F2(c4.z, c4.z), F2(hr[2].x, hr[2].y), yb[tt][0]);
            yb[tt][1] = ffma2(F2(c4.z, c4.z), F2(hr[2].z, hr[2].w), yb[tt][1]);
            yb[tt][0] = ffma2(F2(c4.w, c4.w), F2(hr[3].x, hr[3].y), yb[tt][0]);
            yb[tt][1] = ffma2(F2(c4.w, c4.w), F2(hr[3].z, hr[3].w), yb[tt][1]);
        }
    }
    __syncthreads();

    // ---- inline chunk recurrence: h0 half1 (rows 64..127) ----
    #pragma unroll
    for (int jj = 0; jj < 4; jj++) hreg[jj] = make_float4(0.f, 0.f, 0.f, 0.f);
    for (int j = 0; j < c; j++) {
        float q = expf(-eA * cdg[(size_t)(b * SS + j * L64 + 63) * Hh + h]);
        const float* Sb = Sbase + (size_t)j * 8192;
        #pragma unroll
        for (int jj = 0; jj < 4; jj++) {
            int i = tid + jj * 256;
            int rn = i >> 4, pq = (i & 15) << 2;
            float4 s4 = *(const float4*)&Sb[(64 + rn) * 64 + pq];
            hreg[jj].x = q * hreg[jj].x + s4.x;
            hreg[jj].y = q * hreg[jj].y + s4.y;
            hreg[jj].z = q * hreg[jj].z + s4.z;
            hreg[jj].w = q * hreg[jj].w + s4.w;
        }
    }
    #pragma unroll
    for (int jj = 0; jj < 4; jj++) {
        int i = tid + jj * 256;
        int rn = i >> 4, pq = (i & 15) << 2;
        *(float4*)&h0s[rn * 68 + pq] = hreg[jj];
    }
    __syncthreads();
    for (int rn = 0; rn < 64; rn += 4) {
        float4 cr[4], hr[4];
        #pragma unroll
        for (int r = 0; r < 4; r++) cr[r] = *(const float4*)&Csm[(t0 + r) * 132 + 64 + rn];
        #pragma unroll
        for (int j = 0; j < 4; j++) hr[j] = *(const float4*)&h0s[(rn + j) * 68 + p0];
        #pragma unroll
        for (int tt = 0; tt < 4; tt++) {
            float4 c4 = cr[tt];
            yb[tt][0] = ffma2(F2(c4.x, c4.x), F2(hr[0].x, hr[0].y), yb[tt][0]);
            yb[tt][1] = ffma2(F2(c4.x, c4.x), F2(hr[0].z, hr[0].w), yb[tt][1]);
            yb[tt][0] = ffma2(F2(c4.y, c4.y), F2(hr[1].x, hr[1].y), yb[tt][0]);
            yb[tt][1] = ffma2(F2(c4.y, c4.y), F2(hr[1].z, hr[1].w), yb[tt][1]);
            yb[tt][0] = ffma2(F2(c4.z, c4.z), F2(hr[2].x, hr[2].y), yb[tt][0]);
            yb[tt][1] = ffma2(F2(c4.z, c4.z), F2(hr[2].z, hr[2].w), yb[tt][1]);
            yb[tt][0] = ffma2(F2(c4.w, c4.w), F2(hr[3].x, hr[3].y), yb[tt][0]);
            yb[tt][1] = ffma2(F2(c4.w, c4.w), F2(hr[3].z, hr[3].w), yb[tt][1]);
        }
    }

    #pragma unroll
    for (int tt = 0; tt < 4; tt++) {
        int t = t0 + tt;
        float Qt = __expf(-eA * cds[t]);
        size_t token = (size_t)(tok0 + t);
        float4 uv = *(const float4*)&proj[token * NPROJ + 1024 + h * 64 + p0];
        float4 zv = *(const float4*)&proj[token * NPROJ + h * 64 + p0];
        float y0 = ya[tt][0].x + Qt * yb[tt][0].x;
        float y1 = ya[tt][0].y + Qt * yb[tt][0].y;
        float y2 = ya[tt][1].x + Qt * yb[tt][1].x;
        float y3 = ya[tt][1].y + Qt * yb[tt][1].y;
        float4 o;
        o.x = rnd_tf32((y0 + uv.x * dsk) * (zv.x / (1.f + expf(-zv.x))));
        o.y = rnd_tf32((y1 + uv.y * dsk) * (zv.y / (1.f + expf(-zv.y))));
        o.z = rnd_tf32((y2 + uv.z * dsk) * (zv.z / (1.f + expf(-zv.z))));
        o.w = rnd_tf32((y3 + uv.w * dsk) * (zv.w / (1.f + expf(-zv.w))));
        *(float4*)&gy[token * DIN + h * 64 + p0] = o;
    }
}

// ---------------- launch ----------------
extern "C" void kernel_launch(void* const* d_in, const int* in_sizes, int n_in,
                              void* d_out, int out_size) {
    const float* x      = (const float*)d_in[0];
    const float* mask   = (const float*)d_in[1];
    const float* n1w    = (const float*)d_in[2];
    const float* n2w    = (const float*)d_in[3];
    const float* Wz     = (const float*)d_in[4];
    const float* Wx     = (const float*)d_in[5];
    const float* Wb     = (const float*)d_in[6];
    const float* Wc     = (const float*)d_in[7];
    const float* Wdt    = (const float*)d_in[8];
    const float* dtb    = (const float*)d_in[9];
    const float* A_log  = (const float*)d_in[10];
    const float* D_skip = (const float*)d_in[11];
    const float* Wout   = (const float*)d_in[12];
    const float* w1     = (const float*)d_in[13];
    const float* w2     = (const float*)d_in[14];
    const float* w3     = (const float*)d_in[15];
    float* out = (float*)d_out;

    float *xn, *proj, *gy, *x1, *xn2, *g2;
    float *WpT, *W13T, *WoT, *W2T, *Sg, *cdg;
    cudaGetSymbolAddress((void**)&xn,   g_xn);
    cudaGetSymbolAddress((void**)&proj, g_proj);
    cudaGetSymbolAddress((void**)&gy,   g_gy);
    cudaGetSymbolAddress((void**)&x1,   g_x1);
    cudaGetSymbolAddress((void**)&xn2,  g_xn2);
    cudaGetSymbolAddress((void**)&g2,   g_g2);
    cudaGetSymbolAddress((void**)&WpT,  g_WpT);
    cudaGetSymbolAddress((void**)&W13T, g_W13T);
    cudaGetSymbolAddress((void**)&WoT,  g_WoT);
    cudaGetSymbolAddress((void**)&W2T,  g_W2T);
    cudaGetSymbolAddress((void**)&Sg,   g_S);
    cudaGetSymbolAddress((void**)&cdg,  g_cd);

    const int smemMain = NSTAGE * (ASZ + BSZ) * 4;       // 110,592
    const int smemSk   = NSTAGE * (ASZK + BSZK) * 4;     // 55,296
    const int smemP1   = (128 + 64 * 132 + 64 * 68) * 4;
    const int smemP3   = (64 * 132 * 2 + 64 * 68 * 2 + 64) * 4;
    static int configured = 0;
    if (!configured) {
        cudaFuncSetAttribute(mma_gemm,    cudaFuncAttributeMaxDynamicSharedMemorySize, smemMain);
        cudaFuncSetAttribute(mma_gemm_sk, cudaFuncAttributeMaxDynamicSharedMemorySize, smemSk);
        cudaFuncSetAttribute(scan_pass1,  cudaFuncAttributeMaxDynamicSharedMemorySize, smemP1);
        cudaFuncSetAttribute(scan_pass3,  cudaFuncAttributeMaxDynamicSharedMemorySize, smemP3);
        configured = 1;
    }

    tpack_kernel<<<dim3(196 + N13/32, 16), 256>>>(Wz, Wx, Wb, Wc, Wdt, w1, w3);
    tpack_sk_kernel<<<dim3(32, 44), 256>>>(Wout, w2);
    rmsnorm_kernel<<<TT/2, 256>>>(x, n1w, mask, xn, 1);

    mma_gemm<<<dim3(NPROJ/128, TT/128), 256, smemMain>>>(xn, WpT, proj, TT, NPROJ, Dm, 0, nullptr, nullptr);

    scan_pass1<<<NCHK, 256, smemP1>>>(proj, dtb, A_log, Sg, cdg);
    scan_pass3<<<NCHK, 256, smemP3>>>(proj, cdg, Sg, A_log, D_skip, gy);

    mma_gemm_sk<<<dim3(Dm/64, TT/64), 256, smemSk>>>(gy, WoT, x1, TT, Dm, DIN, 1, x, mask);
    rmsnorm_kernel<<<TT/2, 256>>>(x1, n2w, mask, xn2, 0);

    // w1/w3 interleaved GEMM with fused swiglu epilogue -> g2 directly
    mma_gemm<<<dim3(N13/128, TT/128), 256, smemMain>>>(xn2, W13T, g2, TT, N13, Dm, 5, nullptr, nullptr);
    mma_gemm_sk<<<dim3(Dm/64, TT/64), 256, smemSk>>>(g2, W2T, out, TT, Dm, DFFP, 2, x1, mask);
}

// round 17
// speedup vs baseline: 1.3449x; 1.2749x over previous
#include <cuda_runtime.h>
#include <cuda_fp16.h>
#include <math.h>
#include <stdint.h>

// ---------------- problem constants ----------------
#define Dm     512
#define DIN    1024
#define Hh     16
#define DFF    1368
#define DFFP   1408
#define N13    2816            // w1/w3 column-interleaved
#define NPROJ  6272            // Wz|Wx|Wb|Wc|Wdt(pad)
#define DTC    6144
#define BB     4
#define SS     512
#define TT     2048
#define NCHK   512
#define L64    64

// ---------------- static scratch ----------------
__device__ __align__(16) __half g_xn  [TT*Dm];
__device__ __align__(16) float  g_proj[TT*NPROJ];
__device__ __align__(16) __half g_gy  [TT*DIN];
__device__ __align__(16) float  g_x1  [TT*Dm];
__device__ __align__(16) __half g_xn2 [TT*Dm];
__device__ __align__(16) __half g_g2  [TT*DFFP];
__device__ __align__(16) __half g_WpT [NPROJ*Dm];   // [n][k]
__device__ __align__(16) __half g_W13T[N13*Dm];
__device__ __align__(16) __half g_WoT [Dm*DIN];
__device__ __align__(16) __half g_W2T [Dm*DFFP];
__device__ __align__(16) float  g_S   [NCHK*8192];
__device__ __align__(16) float  g_cd  [TT*Hh];

// ---------------- helpers ----------------
__device__ __forceinline__ uint32_t f2tf32(float v) {
    uint32_t u; asm("cvt.rna.tf32.f32 %0, %1;" : "=r"(u) : "f"(v)); return u;
}
__device__ __forceinline__ float rnd_tf32(float v) { return __uint_as_float(f2tf32(v)); }

#define CP16(dst, src) asm volatile("cp.async.cg.shared.global [%0], [%1], 16;\n" :: "r"(dst), "l"(src))
#define CP_COMMIT()    asm volatile("cp.async.commit_group;\n")
#define CP_WAIT(n)     asm volatile("cp.async.wait_group %0;\n" :: "n"(n))

__device__ __forceinline__ void mma_f16(float* c, const uint32_t* a, const uint32_t* b) {
    asm volatile("mma.sync.aligned.m16n8k16.row.col.f32.f16.f16.f32 "
        "{%0,%1,%2,%3}, {%4,%5,%6,%7}, {%8,%9}, {%0,%1,%2,%3};"
        : "+f"(c[0]), "+f"(c[1]), "+f"(c[2]), "+f"(c[3])
        : "r"(a[0]), "r"(a[1]), "r"(a[2]), "r"(a[3]), "r"(b[0]), "r"(b[1]));
}
__device__ __forceinline__ void ldsm_x4(uint32_t& r0, uint32_t& r1, uint32_t& r2, uint32_t& r3,
                                        uint32_t addr) {
    asm volatile("ldmatrix.sync.aligned.m8n8.x4.shared.b16 {%0,%1,%2,%3}, [%4];"
        : "=r"(r0), "=r"(r1), "=r"(r2), "=r"(r3) : "r"(addr));
}
__device__ __forceinline__ float2 ffma2(float2 a, float2 b, float2 c) {
    unsigned long long A = *reinterpret_cast<unsigned long long*>(&a);
    unsigned long long B = *reinterpret_cast<unsigned long long*>(&b);
    unsigned long long C = *reinterpret_cast<unsigned long long*>(&c);
    unsigned long long D;
    asm("fma.rn.f32x2 %0, %1, %2, %3;" : "=l"(D) : "l"(A), "l"(B), "l"(C));
    return *reinterpret_cast<float2*>(&D);
}
#define F2(a,b) make_float2((a),(b))

// ---------------- transposed pack: Wp | W13 (w1/w3 interleaved), fp16 ----------------
__global__ __launch_bounds__(256)
void tpack_kernel(const float* __restrict__ Wz, const float* __restrict__ Wx,
                  const float* __restrict__ Wb, const float* __restrict__ Wc,
                  const float* __restrict__ Wdt,
                  const float* __restrict__ w1, const float* __restrict__ w3) {
    __shared__ float tile[32][33];
    const int bx = blockIdx.x, by = blockIdx.y;
    const int tx = threadIdx.x & 31, ty = threadIdx.x >> 5;
    const int r0 = by * 32;
    int mat, c0;
    if (bx < 196) { mat = 0; c0 = bx * 32; }
    else          { mat = 1; c0 = (bx - 196) * 32; }

    #pragma unroll
    for (int i = 0; i < 32; i += 8) {
        int r = r0 + ty + i, c = c0 + tx;
        float v;
        if (mat == 0) {
            if      (c < 1024) v = Wz[r * 1024 + c];
            else if (c < 2048) v = Wx[r * 1024 + c - 1024];
            else if (c < 4096) v = Wb[r * 2048 + c - 2048];
            else if (c < 6144) v = Wc[r * 2048 + c - 4096];
            else if (c < 6160) v = Wdt[r * 16 + c - 6144];
            else               v = 0.f;
        } else {
            v = 0.f;
            if (c < 2 * DFF) {
                const float* w = (c & 1) ? w3 : w1;
                v = w[r * DFF + (c >> 1)];
            }
        }
        tile[ty + i][tx] = v;
    }
    __syncthreads();
    __half* out = (mat == 0) ? g_WpT : g_W13T;
    #pragma unroll
    for (int i = 0; i < 32; i += 8)
        out[(size_t)(c0 + ty + i) * Dm + r0 + tx] = __float2half(tile[tx][ty + i]);
}

// ---------------- transposed pack: Wout, w2, fp16 ----------------
__global__ __launch_bounds__(256)
void tpack_sk_kernel(const float* __restrict__ Wout, const float* __restrict__ w2) {
    __shared__ float tile[32][33];
    const int bx = blockIdx.x, by = blockIdx.y;
    const int tx = threadIdx.x & 31, ty = threadIdx.x >> 5;
    const int mat = (bx < 16) ? 0 : 1;
    const int c0 = ((mat == 0) ? bx : bx - 16) * 32;
    const int r0 = by * 32;
    if (mat == 0 && r0 >= DIN) return;

    #pragma unroll
    for (int i = 0; i < 32; i += 8) {
        int r = r0 + ty + i, c = c0 + tx;
        float v;
        if (mat == 0) v = Wout[(size_t)r * 512 + c];
        else          v = (r < DFF) ? w2[(size_t)r * 512 + c] : 0.f;
        tile[ty + i][tx] = v;
    }
    __syncthreads();
    __half* out = mat ? g_W2T : g_WoT;
    const int ld = mat ? DFFP : DIN;
    #pragma unroll
    for (int i = 0; i < 32; i += 8)
        out[(size_t)(c0 + ty + i) * ld + r0 + tx] = __float2half(tile[tx][ty + i]);
}

// ---------------- rmsnorm: 2 tokens per block, fp16 output ----------------
__global__ __launch_bounds__(256)
void rmsnorm_kernel(const float* __restrict__ x, const float* __restrict__ w,
                    const float* __restrict__ mask, __half* __restrict__ out, int useMask) {
    const int half_ = threadIdx.x >> 7;
    const int li    = threadIdx.x & 127;
    const int t     = blockIdx.x * 2 + half_;
    const float4* xr = (const float4*)(x + (size_t)t * Dm);
    float4 v = xr[li];
    float s = v.x * v.x + v.y * v.y + v.z * v.z + v.w * v.w;
    __shared__ float red[8];
    #pragma unroll
    for (int o = 16; o; o >>= 1) s += __shfl_down_sync(0xFFFFFFFFu, s, o);
    if ((threadIdx.x & 31) == 0) red[threadIdx.x >> 5] = s;
    __syncthreads();
    const float* rh = red + half_ * 4;
    float tot = rh[0] + rh[1] + rh[2] + rh[3];
    float inv = rsqrtf(tot / (float)Dm + 1e-6f);
    float m = useMask ? mask[t] : 1.f;
    inv *= m;
    float4 wv = ((const float4*)w)[li];
    __half2* o2 = (__half2*)(out + (size_t)t * Dm + li * 4);
    o2[0] = __floats2half2_rn(v.x * inv * wv.x, v.y * inv * wv.y);
    o2[1] = __floats2half2_rn(v.z * inv * wv.z, v.w * inv * wv.w);
}

// ---------------- fp16 GEMM, 128x128, 256 threads (8 warps 4x2), ldmatrix ----------------
// mode 0: C=acc(fp32)   1: C=res+acc*mask[row]   2: C=(res+acc)*mask
// mode 5: fused swiglu -> half output, stride N/2
#define NSTAGE 3
#define APITCH 40            // halves per row (32 + 8 pad)
#define ASZH (128*APITCH)    // halves per stage per operand
__global__ __launch_bounds__(256, 2)
void mma_gemm(const __half* __restrict__ A, const __half* __restrict__ BT,
              float* __restrict__ C, int M, int N, int K,
              int mode, const float* __restrict__ res, const float* __restrict__ mask) {
    extern __shared__ __half smh[];
    __half* Asm = smh;
    __half* Bsm = smh + NSTAGE * ASZH;
    const uint32_t as_sh = (uint32_t)__cvta_generic_to_shared(Asm);
    const uint32_t bs_sh = (uint32_t)__cvta_generic_to_shared(Bsm);

    const int bm = blockIdx.y * 128, bn = blockIdx.x * 128;
    const int tid = threadIdx.x;
    const int lane = tid & 31, w = tid >> 5;
    const int wm = (w >> 1) * 32, wn = (w & 1) * 64;
    const int g = lane >> 2, tg = lane & 3;
    const int kIter = K >> 5;

    const int am0 = tid >> 2, akq = (tid & 3) * 8;   // rows 0..63 (+64), 8-half chunks

    auto issue = [&](int it) {
        const int st = it % NSTAGE;
        const int k0 = it << 5;
        #pragma unroll
        for (int i = 0; i < 2; i++) {
            int m = am0 + i * 64;
            CP16(as_sh + (st * ASZH + m * APITCH + akq) * 2,
                 A + (size_t)(bm + m) * K + k0 + akq);
        }
        #pragma unroll
        for (int i = 0; i < 2; i++) {
            int n = am0 + i * 64;
            CP16(bs_sh + (st * ASZH + n * APITCH + akq) * 2,
                 BT + (size_t)(bn + n) * K + k0 + akq);
        }
        CP_COMMIT();
    };

    const int tq = lane & 7, sel = lane >> 3;
    uint32_t aBase[2], bBase[4];
    #pragma unroll
    for (int mt = 0; mt < 2; mt++)
        aBase[mt] = as_sh + (((wm + mt * 16 + (sel & 1) * 8 + tq) * APITCH + (sel >> 1) * 8) << 1);
    #pragma unroll
    for (int j = 0; j < 4; j++)
        bBase[j] = bs_sh + (((wn + j * 16 + (sel >> 1) * 8 + tq) * APITCH + (sel & 1) * 8) << 1);

    float acc[2][8][4];
    #pragma unroll
    for (int mt = 0; mt < 2; mt++)
        #pragma unroll
        for (int nt = 0; nt < 8; nt++)
            #pragma unroll
            for (int q = 0; q < 4; q++) acc[mt][nt][q] = 0.f;

    issue(0); issue(1);

    for (int it = 0; it < kIter; it++) {
        if (it == kIter - 1) { CP_WAIT(0); } else { CP_WAIT(1); }
        __syncthreads();
        if (it + 2 < kIter) issue(it + 2);

        const uint32_t soA = (uint32_t)((it % NSTAGE) * ASZH) << 1;
        #pragma unroll
        for (int ks = 0; ks < 2; ks++) {
            const uint32_t kbb = (uint32_t)(ks * 16) << 1;    // 16 halves
            uint32_t af[2][4];
            ldsm_x4(af[0][0], af[0][1], af[0][2], af[0][3], aBase[0] + soA + kbb);
            ldsm_x4(af[1][0], af[1][1], af[1][2], af[1][3], aBase[1] + soA + kbb);
            #pragma unroll
            for (int j = 0; j < 4; j++) {
                uint32_t b0, b1, b2, b3;
                ldsm_x4(b0, b1, b2, b3, bBase[j] + soA + kbb);
                uint32_t bf0[2] = {b0, b1};
                uint32_t bf1[2] = {b2, b3};
                mma_f16(acc[0][2 * j],     af[0], bf0);
                mma_f16(acc[1][2 * j],     af[1], bf0);
                mma_f16(acc[0][2 * j + 1], af[0], bf1);
                mma_f16(acc[1][2 * j + 1], af[1], bf1);
            }
        }
    }

    if (mode == 5) {
        __half* Ch = (__half*)C;
        const int halfN = N >> 1;
        #pragma unroll
        for (int mt = 0; mt < 2; mt++) {
            #pragma unroll
            for (int nt = 0; nt < 8; nt++) {
                int r0 = bm + wm + mt * 16 + g;
                int c0 = bn + wn + nt * 8 + tg * 2;
                #pragma unroll
                for (int half_ = 0; half_ < 2; half_++) {
                    int r = r0 + half_ * 8;
                    float v0 = acc[mt][nt][half_ * 2 + 0];
                    float v1 = acc[mt][nt][half_ * 2 + 1];
                    float sv = v0 / (1.f + expf(-v0));
                    Ch[(size_t)r * halfN + (c0 >> 1)] = __float2half(sv * v1);
                }
            }
        }
        return;
    }

    #pragma unroll
    for (int mt = 0; mt < 2; mt++) {
        #pragma unroll
        for (int nt = 0; nt < 8; nt++) {
            int r0 = bm + wm + mt * 16 + g;
            int c0 = bn + wn + nt * 8 + tg * 2;
            #pragma unroll
            for (int half_ = 0; half_ < 2; half_++) {
                int r = r0 + half_ * 8;
                float mk = (mode == 1 || mode == 2) ? mask[r] : 0.f;
                #pragma unroll
                for (int q = 0; q < 2; q++) {
                    int c = c0 + q;
                    float v = acc[mt][nt][half_ * 2 + q];
                    size_t idx = (size_t)r * N + c;
                    float o;
                    if (mode == 0)      o = v;
                    else if (mode == 1) o = res[idx] + v * mk;
                    else                o = (res[idx] + v) * mk;
                    C[idx] = o;
                }
            }
        }
    }
}

// ---------------- fp16 GEMM, 64x64 tile (skinny: Wout, w2) ----------------
#define ASZKH (64*APITCH)
__global__ __launch_bounds__(256, 3)
void mma_gemm_sk(const __half* __restrict__ A, const __half* __restrict__ BT,
                 float* __restrict__ C, int M, int N, int K,
                 int mode, const float* __restrict__ res, const float* __restrict__ mask) {
    extern __shared__ __half smh[];
    __half* Asm = smh;
    __half* Bsm = smh + NSTAGE * ASZKH;
    const uint32_t as_sh = (uint32_t)__cvta_generic_to_shared(Asm);
    const uint32_t bs_sh = (uint32_t)__cvta_generic_to_shared(Bsm);

    const int bm = blockIdx.y * 64, bn = blockIdx.x * 64;
    const int tid = threadIdx.x;
    const int lane = tid & 31, w = tid >> 5;
    const int wm = (w & 1) * 32, wn = (w >> 1) * 16;
    const int g = lane >> 2, tg = lane & 3;
    const int kIter = K >> 5;

    const int am0 = tid >> 2, akq = (tid & 3) * 8;   // rows 0..63, one chunk each

    auto issue = [&](int it) {
        const int st = it % NSTAGE;
        const int k0 = it << 5;
        CP16(as_sh + (st * ASZKH + am0 * APITCH + akq) * 2,
             A + (size_t)(bm + am0) * K + k0 + akq);
        CP16(bs_sh + (st * ASZKH + am0 * APITCH + akq) * 2,
             BT + (size_t)(bn + am0) * K + k0 + akq);
        CP_COMMIT();
    };

    const int tq = lane & 7, sel = lane >> 3;
    uint32_t aBase[2], bBase;
    #pragma unroll
    for (int mt = 0; mt < 2; mt++)
        aBase[mt] = as_sh + (((wm + mt * 16 + (sel & 1) * 8 + tq) * APITCH + (sel >> 1) * 8) << 1);
    bBase = bs_sh + (((wn + (sel >> 1) * 8 + tq) * APITCH + (sel & 1) * 8) << 1);

    float acc[2][2][4];
    #pragma unroll
    for (int mt = 0; mt < 2; mt++)
        #pragma unroll
        for (int nt = 0; nt < 2; nt++)
            #pragma unroll
            for (int q = 0; q < 4; q++) acc[mt][nt][q] = 0.f;

    issue(0); issue(1);

    for (int it = 0; it < kIter; it++) {
        if (it == kIter - 1) { CP_WAIT(0); } else { CP_WAIT(1); }
        __syncthreads();
        if (it + 2 < kIter) issue(it + 2);

        const uint32_t soA = (uint32_t)((it % NSTAGE) * ASZKH) << 1;
        #pragma unroll
        for (int ks = 0; ks < 2; ks++) {
            const uint32_t kbb = (uint32_t)(ks * 16) << 1;
            uint32_t af[2][4];
            ldsm_x4(af[0][0], af[0][1], af[0][2], af[0][3], aBase[0] + soA + kbb);
            ldsm_x4(af[1][0], af[1][1], af[1][2], af[1][3], aBase[1] + soA + kbb);
            uint32_t b0, b1, b2, b3;
            ldsm_x4(b0, b1, b2, b3, bBase + soA + kbb);
            uint32_t bf0[2] = {b0, b1};
            uint32_t bf1[2] = {b2, b3};
            mma_f16(acc[0][0], af[0], bf0);
            mma_f16(acc[1][0], af[1], bf0);
            mma_f16(acc[0][1], af[0], bf1);
            mma_f16(acc[1][1], af[1], bf1);
        }
    }

    #pragma unroll
    for (int mt = 0; mt < 2; mt++) {
        #pragma unroll
        for (int nt = 0; nt < 2; nt++) {
            int r0 = bm + wm + mt * 16 + g;
            int c0 = bn + wn + nt * 8 + tg * 2;
            #pragma unroll
            for (int half_ = 0; half_ < 2; half_++) {
                int r = r0 + half_ * 8;
                float mk = (mode == 1 || mode == 2) ? mask[r] : 0.f;
                #pragma unroll
                for (int q = 0; q < 2; q++) {
                    int c = c0 + q;
                    float v = acc[mt][nt][half_ * 2 + q];
                    size_t idx = (size_t)r * N + c;
                    float o;
                    if (mode == 0)      o = v;
                    else if (mode == 1) o = res[idx] + v * mk;
                    else                o = (res[idx] + v) * mk;
                    C[idx] = o;
                }
            }
        }
    }
}

// ================= chunked SSM scan (fp32, unchanged math) =================
__global__ __launch_bounds__(256, 2)
void scan_pass1(const float* __restrict__ proj, const float* __restrict__ dtb,
                const float* __restrict__ A_log,
                float* __restrict__ Sg, float* __restrict__ cdg) {
    const int blk = blockIdx.x;
    const int c = blk & 7, bh = blk >> 3, h = bh & 15, b = bh >> 4;
    const int tid = threadIdx.x;
    const int tok0 = b * SS + c * L64;

    extern __shared__ float sm1[];
    float* cds = sm1;
    float* wts = sm1 + 64;
    float* Bw  = sm1 + 128;
    float* Ud  = Bw + 64 * 132;

    const float eA = expf(A_log[h]);

    if (tid < 64) {
        float raw = proj[(size_t)(tok0 + tid) * NPROJ + DTC + h] + dtb[h];
        cds[tid] = (raw > 20.f) ? raw : log1pf(expf(raw));
    }
    __syncthreads();
    #pragma unroll
    for (int off = 1; off < 64; off <<= 1) {
        float v = (tid < 64 && tid >= off) ? cds[tid - off] : 0.f;
        __syncthreads();
        if (tid < 64) cds[tid] += v;
        __syncthreads();
    }
    if (tid < 64) {
        cdg[(size_t)(tok0 + tid) * Hh + h] = cds[tid];
        wts[tid] = expf(-eA * (cds[63] - cds[tid]));
    }
    __syncthreads();

    for (int i = tid; i < 64 * 32; i += 256) {
        int t = i >> 5, rq = (i & 31) << 2;
        float4 bv = *(const float4*)&proj[(size_t)(tok0 + t) * NPROJ + 2048 + h * 128 + rq];
        float w = wts[t];
        float4 o; o.x = bv.x * w; o.y = bv.y * w; o.z = bv.z * w; o.w = bv.w * w;
        *(float4*)&Bw[t * 132 + rq] = o;
    }
    for (int i = tid; i < 64 * 16; i += 256) {
        int t = i >> 4, pq = (i & 15) << 2;
        float4 uv = *(const float4*)&proj[(size_t)(tok0 + t) * NPROJ + 1024 + h * 64 + pq];
        float dtv = (t == 0) ? cds[0] : (cds[t] - cds[t - 1]);
        float4 o; o.x = uv.x * dtv; o.y = uv.y * dtv; o.z = uv.z * dtv; o.w = uv.w * dtv;
        *(float4*)&Ud[t * 68 + pq] = o;
    }
    __syncthreads();

    const int rn0 = (tid >> 3) * 4, p0 = (tid & 7) * 8;
    float2 acc[4][4];
    #pragma unroll
    for (int r = 0; r < 4; r++)
        #pragma unroll
        for (int j = 0; j < 4; j++) acc[r][j] = F2(0.f, 0.f);

    for (int t = 0; t < 64; t++) {
        float4 bb = *(const float4*)&Bw[t * 132 + rn0];
        float4 u0 = *(const float4*)&Ud[t * 68 + p0];
        float4 u1 = *(const float4*)&Ud[t * 68 + p0 + 4];
        float br[4] = {bb.x, bb.y, bb.z, bb.w};
        float2 ua = F2(u0.x, u0.y), ub = F2(u0.z, u0.w);
        float2 uc = F2(u1.x, u1.y), ue = F2(u1.z, u1.w);
        #pragma unroll
        for (int r = 0; r < 4; r++) {
            float2 b2 = F2(br[r], br[r]);
            acc[r][0] = ffma2(b2, ua, acc[r][0]);
            acc[r][1] = ffma2(b2, ub, acc[r][1]);
            acc[r][2] = ffma2(b2, uc, acc[r][2]);
            acc[r][3] = ffma2(b2, ue, acc[r][3]);
        }
    }
    float* Sb = Sg + (size_t)blk * 8192;
    #pragma unroll
    for (int r = 0; r < 4; r++) {
        float4 o0; o0.x = acc[r][0].x; o0.y = acc[r][0].y; o0.z = acc[r][1].x; o0.w = acc[r][1].y;
        float4 o1; o1.x = acc[r][2].x; o1.y = acc[r][2].y; o1.z = acc[r][3].x; o1.w = acc[r][3].y;
        *(float4*)&Sb[(rn0 + r) * 64 + p0]     = o0;
        *(float4*)&Sb[(rn0 + r) * 64 + p0 + 4] = o1;
    }
}

// Pass 3 (inline chunk recurrence), gy output as fp16
__global__ __launch_bounds__(256, 2)
void scan_pass3(const float* __restrict__ proj, const float* __restrict__ cdg,
                const float* __restrict__ Sg, const float* __restrict__ A_log,
                const float* __restrict__ Dskip, __half* __restrict__ gy) {
    const int blk = blockIdx.x;
    const int c = blk & 7, bh = blk >> 3, h = bh & 15, b = bh >> 4;
    const int tid = threadIdx.x;
    const int tok0 = b * SS + c * L64;
    const float eA  = expf(A_log[h]);
    const float dsk = Dskip[h];

    extern __shared__ float sm3[];
    float* Csm  = sm3;
    float* Bsm  = Csm + 64 * 132;
    float* Udsm = Bsm + 64 * 132;
    float* Msm  = Udsm + 64 * 68;
    float* cds  = Msm + 64 * 68;

    if (tid < 64) cds[tid] = cdg[(size_t)(tok0 + tid) * Hh + h];
    for (int i = tid; i < 64 * 32; i += 256) {
        int t = i >> 5, rq = (i & 31) << 2;
        const float* src = &proj[(size_t)(tok0 + t) * NPROJ + 2048 + h * 128 + rq];
        *(float4*)&Bsm[t * 132 + rq] = *(const float4*)src;
        *(float4*)&Csm[t * 132 + rq] = *(const float4*)(src + 2048);
    }
    __syncthreads();
    for (int i = tid; i < 64 * 16; i += 256) {
        int t = i >> 4, pq = (i & 15) << 2;
        float4 uv = *(const float4*)&proj[(size_t)(tok0 + t) * NPROJ + 1024 + h * 64 + pq];
        float dtv = (t == 0) ? cds[0] : (cds[t] - cds[t - 1]);
        float4 o; o.x = uv.x * dtv; o.y = uv.y * dtv; o.z = uv.z * dtv; o.w = uv.w * dtv;
        *(float4*)&Udsm[t * 68 + pq] = o;
    }
    __syncthreads();

    const int t0 = (tid >> 4) * 4;
    const int q0 = (tid & 15) * 4;

    float2 ga[4][4];
    #pragma unroll
    for (int i = 0; i < 4; i++)
        #pragma unroll
        for (int j = 0; j < 4; j++) ga[i][j] = F2(0.f, 0.f);
    for (int k = 0; k < 128; k += 4) {
        float4 cr[4], br[4];
        #pragma unroll
        for (int r = 0; r < 4; r++) {
            cr[r] = *(const float4*)&Csm[(t0 + r) * 132 + k];
            br[r] = *(const float4*)&Bsm[(q0 + r) * 132 + k];
        }
        #pragma unroll
        for (int tt = 0; tt < 4; tt++) {
            float2 c2a = F2(cr[tt].x, cr[tt].y), c2b = F2(cr[tt].z, cr[tt].w);
            #pragma unroll
            for (int qq = 0; qq < 4; qq++) {
                ga[tt][qq] = ffma2(c2a, F2(br[qq].x, br[qq].y), ga[tt][qq]);
                ga[tt][qq] = ffma2(c2b, F2(br[qq].z, br[qq].w), ga[tt][qq]);
            }
        }
    }
    #pragma unroll
    for (int tt = 0; tt < 4; tt++) {
        int t = t0 + tt;
        #pragma unroll
        for (int qq = 0; qq < 4; qq++) {
            int q = q0 + qq;
            float g = ga[tt][qq].x + ga[tt][qq].y;
            float w = (q <= t) ? __expf(-eA * (cds[t] - cds[q])) : 0.f;
            Msm[t * 68 + q] = g * w;
        }
    }
    __syncthreads();

    const float* Sbase = Sg + (size_t)(bh * 8) * 8192;
    float4 hreg[4];
    #pragma unroll
    for (int jj = 0; jj < 4; jj++) hreg[jj] = make_float4(0.f, 0.f, 0.f, 0.f);
    for (int j = 0; j < c; j++) {
        float q = expf(-eA * cdg[(size_t)(b * SS + j * L64 + 63) * Hh + h]);
        const float* Sb = Sbase + (size_t)j * 8192;
        #pragma unroll
        for (int jj = 0; jj < 4; jj++) {
            int i = tid + jj * 256;
            int rn = i >> 4, pq = (i & 15) << 2;
            float4 s4 = *(const float4*)&Sb[rn * 64 + pq];
            hreg[jj].x = q * hreg[jj].x + s4.x;
            hreg[jj].y = q * hreg[jj].y + s4.y;
            hreg[jj].z = q * hreg[jj].z + s4.z;
            hreg[jj].w = q * hreg[jj].w + s4.w;
        }
    }

    const int p0 = q0;
    float2 ya[4][2], yb[4][2];
    #pragma unroll
    for (int i = 0; i < 4; i++) {
        ya[i][0] = F2(0.f, 0.f); ya[i][1] = F2(0.f, 0.f);
        yb[i][0] = F2(0.f, 0.f); yb[i][1] = F2(0.f, 0.f);
    }
    for (int q = 0; q < 64; q += 4) {
        float4 mr[4], ur[4];
        #pragma unroll
        for (int r = 0; r < 4; r++) mr[r] = *(const float4*)&Msm[(t0 + r) * 68 + q];
        #pragma unroll
        for (int j = 0; j < 4; j++) ur[j] = *(const float4*)&Udsm[(q + j) * 68 + p0];
        #pragma unroll
        for (int tt = 0; tt < 4; tt++) {
            float4 m4 = mr[tt];
            ya[tt][0] = ffma2(F2(m4.x, m4.x), F2(ur[0].x, ur[0].y), ya[tt][0]);
            ya[tt][1] = ffma2(F2(m4.x, m4.x), F2(ur[0].z, ur[0].w), ya[tt][1]);
            ya[tt][0] = ffma2(F2(m4.y, m4.y), F2(ur[1].x, ur[1].y), ya[tt][0]);
            ya[tt][1] = ffma2(F2(m4.y, m4.y), F2(ur[1].z, ur[1].w), ya[tt][1]);
            ya[tt][0] = ffma2(F2(m4.z, m4.z), F2(ur[2].x, ur[2].y), ya[tt][0]);
            ya[tt][1] = ffma2(F2(m4.z, m4.z), F2(ur[2].z, ur[2].w), ya[tt][1]);
            ya[tt][0] = ffma2(F2(m4.w, m4.w), F2(ur[3].x, ur[3].y), ya[tt][0]);
            ya[tt][1] = ffma2(F2(m4.w, m4.w), F2(ur[3].z, ur[3].w), ya[tt][1]);
        }
    }

    float* h0s = Bsm;
    #pragma unroll
    for (int jj = 0; jj < 4; jj++) {
        int i = tid + jj * 256;
        int rn = i >> 4, pq = (i & 15) << 2;
        *(float4*)&h0s[rn * 68 + pq] = hreg[jj];
    }
    __syncthreads();

    for (int rn = 0; rn < 64; rn += 4) {
        float4 cr[4], hr[4];
        #pragma unroll
        for (int r = 0; r < 4; r++) cr[r] = *(const float4*)&Csm[(t0 + r) * 132 + rn];
        #pragma unroll
        for (int j = 0; j < 4; j++) hr[j] = *(const float4*)&h0s[(rn + j) * 68 + p0];
        #pragma unroll
        for (int tt = 0; tt < 4; tt++) {
            float4 c4 = cr[tt];
            yb[tt][0] = ffma2(F2(c4.x, c4.x), F2(hr[0].x, hr[0].y), yb[tt][0]);
            yb[tt][1] = ffma2(F2(c4.x, c4.x), F2(hr[0].z, hr[0].w), yb[tt][1]);
            yb[tt][0] = ffma2(F2(c4.y, c4.y), F2(hr[1].x, hr[1].y), yb[tt][0]);
            yb[tt][1] = ffma2(F2(c4.y, c4.y), F2(hr[1].z, hr[1].w), yb[tt][1]);
            yb[tt][0] = ffma2(F2(c4.z, c4.z), F2(hr[2].x, hr[2].y), yb[tt][0]);
            yb[tt][1] = ffma2(F2(c4.z, c4.z), F2(hr[2].z, hr[2].w), yb[tt][1]);
            yb[tt][0] = ffma2(F2(c4.w, c4.w), F2(hr[3].x, hr[3].y), yb[tt][0]);
            yb[tt][1] = ffma2(F2(c4.w, c4.w), F2(hr[3].z, hr[3].w), yb[tt][1]);
        }
    }
    __syncthreads();

    #pragma unroll
    for (int jj = 0; jj < 4; jj++) hreg[jj] = make_float4(0.f, 0.f, 0.f, 0.f);
    for (int j = 0; j < c; j++) {
        float q = expf(-eA * cdg[(size_t)(b * SS + j * L64 + 63) * Hh + h]);
        const float* Sb = Sbase + (size_t)j * 8192;
        #pragma unroll
        for (int jj = 0; jj < 4; jj++) {
            int i = tid + jj * 256;
            int rn = i >> 4, pq = (i & 15) << 2;
            float4 s4 = *(const float4*)&Sb[(64 + rn) * 64 + pq];
            hreg[jj].x = q * hreg[jj].x + s4.x;
            hreg[jj].y = q * hreg[jj].y + s4.y;
            hreg[jj].z = q * hreg[jj].z + s4.z;
            hreg[jj].w = q * hreg[jj].w + s4.w;
        }
    }
    #pragma unroll
    for (int jj = 0; jj < 4; jj++) {
        int i = tid + jj * 256;
        int rn = i >> 4, pq = (i & 15) << 2;
        *(float4*)&h0s[rn * 68 + pq] = hreg[jj];
    }
    __syncthreads();
    for (int rn = 0; rn < 64; rn += 4) {
        float4 cr[4], hr[4];
        #pragma unroll
        for (int r = 0; r < 4; r++) cr[r] = *(const float4*)&Csm[(t0 + r) * 132 + 64 + rn];
        #pragma unroll
        for (int j = 0; j < 4; j++) hr[j] = *(const float4*)&h0s[(rn + j) * 68 + p0];
        #pragma unroll
        for (int tt = 0; tt < 4; tt++) {
            float4 c4 = cr[tt];
            yb[tt][0] = ffma2(F2(c4.x, c4.x), F2(hr[0].x, hr[0].y), yb[tt][0]);
            yb[tt][1] = ffma2(F2(c4.x, c4.x), F2(hr[0].z, hr[0].w), yb[tt][1]);
            yb[tt][0] = ffma2(F2(c4.y, c4.y), F2(hr[1].x, hr[1].y), yb[tt][0]);
            yb[tt][1] = ffma2(F2(c4.y, c4.y), F2(hr[1].z, hr[1].w), yb[tt][1]);
            yb[tt][0] = ffma2(F2(c4.z, c4.z), F2(hr[2].x, hr[2].y), yb[tt][0]);
            yb[tt][1] = ffma2(F2(c4.z, c4.z), F2(hr[2].z, hr[2].w), yb[tt][1]);
            yb[tt][0] = ffma2(F2(c4.w, c4.w), F2(hr[3].x, hr[3].y), yb[tt][0]);
            yb[tt][1] = ffma2(F2(c4.w, c4.w), F2(hr[3].z, hr[3].w), yb[tt][1]);
        }
    }

    #pragma unroll
    for (int tt = 0; tt < 4; tt++) {
        int t = t0 + tt;
        float Qt = __expf(-eA * cds[t]);
        size_t token = (size_t)(tok0 + t);
        float4 uv = *(const float4*)&proj[token * NPROJ + 1024 + h * 64 + p0];
        float4 zv = *(const float4*)&proj[token * NPROJ + h * 64 + p0];
        float y0 = ya[tt][0].x + Qt * yb[tt][0].x;
        float y1 = ya[tt][0].y + Qt * yb[tt][0].y;
        float y2 = ya[tt][1].x + Qt * yb[tt][1].x;
        float y3 = ya[tt][1].y + Qt * yb[tt][1].y;
        __half2* gp = (__half2*)(gy + token * DIN + h * 64 + p0);
        gp[0] = __floats2half2_rn((y0 + uv.x * dsk) * (zv.x / (1.f + expf(-zv.x))),
                                  (y1 + uv.y * dsk) * (zv.y / (1.f + expf(-zv.y))));
        gp[1] = __floats2half2_rn((y2 + uv.z * dsk) * (zv.z / (1.f + expf(-zv.z))),
                                  (y3 + uv.w * dsk) * (zv.w / (1.f + expf(-zv.w))));
    }
}

// ---------------- launch ----------------
extern "C" void kernel_launch(void* const* d_in, const int* in_sizes, int n_in,
                              void* d_out, int out_size) {
    const float* x      = (const float*)d_in[0];
    const float* mask   = (const float*)d_in[1];
    const float* n1w    = (const float*)d_in[2];
    const float* n2w    = (const float*)d_in[3];
    const float* Wz     = (const float*)d_in[4];
    const float* Wx     = (const float*)d_in[5];
    const float* Wb     = (const float*)d_in[6];
    const float* Wc     = (const float*)d_in[7];
    const float* Wdt    = (const float*)d_in[8];
    const float* dtb    = (const float*)d_in[9];
    const float* A_log  = (const float*)d_in[10];
    const float* D_skip = (const float*)d_in[11];
    const float* Wout   = (const float*)d_in[12];
    const float* w1     = (const float*)d_in[13];
    const float* w2     = (const float*)d_in[14];
    const float* w3     = (const float*)d_in[15];
    float* out = (float*)d_out;

    float *proj, *x1, *Sg, *cdg;
    __half *xn, *gy, *xn2, *g2, *WpT, *W13T, *WoT, *W2T;
    cudaGetSymbolAddress((void**)&xn,   g_xn);
    cudaGetSymbolAddress((void**)&proj, g_proj);
    cudaGetSymbolAddress((void**)&gy,   g_gy);
    cudaGetSymbolAddress((void**)&x1,   g_x1);
    cudaGetSymbolAddress((void**)&xn2,  g_xn2);
    cudaGetSymbolAddress((void**)&g2,   g_g2);
    cudaGetSymbolAddress((void**)&WpT,  g_WpT);
    cudaGetSymbolAddress((void**)&W13T, g_W13T);
    cudaGetSymbolAddress((void**)&WoT,  g_WoT);
    cudaGetSymbolAddress((void**)&W2T,  g_W2T);
    cudaGetSymbolAddress((void**)&Sg,   g_S);
    cudaGetSymbolAddress((void**)&cdg,  g_cd);

    const int smemMain = NSTAGE * ASZH * 2 * 2;          // 61,440
    const int smemSk   = NSTAGE * ASZKH * 2 * 2;         // 30,720
    const int smemP1   = (128 + 64 * 132 + 64 * 68) * 4;
    const int smemP3   = (64 * 132 * 2 + 64 * 68 * 2 + 64) * 4;
    static int configured = 0;
    if (!configured) {
        cudaFuncSetAttribute(mma_gemm,    cudaFuncAttributeMaxDynamicSharedMemorySize, smemMain);
        cudaFuncSetAttribute(mma_gemm_sk, cudaFuncAttributeMaxDynamicSharedMemorySize, smemSk);
        cudaFuncSetAttribute(scan_pass1,  cudaFuncAttributeMaxDynamicSharedMemorySize, smemP1);
        cudaFuncSetAttribute(scan_pass3,  cudaFuncAttributeMaxDynamicSharedMemorySize, smemP3);
        configured = 1;
    }

    tpack_kernel<<<dim3(196 + N13/32, 16), 256>>>(Wz, Wx, Wb, Wc, Wdt, w1, w3);
    tpack_sk_kernel<<<dim3(32, 44), 256>>>(Wout, w2);
    rmsnorm_kernel<<<TT/2, 256>>>(x, n1w, mask, xn, 1);

    mma_gemm<<<dim3(NPROJ/128, TT/128), 256, smemMain>>>(xn, WpT, proj, TT, NPROJ, Dm, 0, nullptr, nullptr);

    scan_pass1<<<NCHK, 256, smemP1>>>(proj, dtb, A_log, Sg, cdg);
    scan_pass3<<<NCHK, 256, smemP3>>>(proj, cdg, Sg, A_log, D_skip, gy);

    mma_gemm_sk<<<dim3(Dm/64, TT/64), 256, smemSk>>>(gy, WoT, x1, TT, Dm, DIN, 1, x, mask);
    rmsnorm_kernel<<<TT/2, 256>>>(x1, n2w, mask, xn2, 0);

    mma_gemm<<<dim3(N13/128, TT/128), 256, smemMain>>>(xn2, W13T, (float*)g2, TT, N13, Dm, 5, nullptr, nullptr);
    mma_gemm_sk<<<dim3(Dm/64, TT/64), 256, smemSk>>>(g2, W2T, out, TT, Dm, DFFP, 2, x1, mask);
}